// round 9
// baseline (speedup 1.0000x reference)
#include <cuda_runtime.h>
#include <cuda_bf16.h>
#include <cstdint>

#define NN 20000
#define EE 320000
#define EA 340000      // E + N self loops
#define HIDD 768
#define NH 8
#define NC 96
#define NL 16
#define NGB 16
#define EMB 512
#define KCAT 2304      // 3 * HIDD (bf16 split: hi*hi + lo*hi + hi*lo)
#define MAXD 64        // smem alpha cache cap (recompute path beyond)

// ---------------- scratch (device globals; no allocations) ----------------
__device__ float d_h[NN * HIDD];
__device__ float d_g[NN * HIDD];
__device__ float d_as[NN * NH];
__device__ float d_ad[NN * NH];
__device__ int   d_deg[NN];
__device__ int   d_rowptr[NN + 1];
__device__ int   d_cursor[NN];
__device__ int   d_csrsrc[EA];
__device__ int   d_gstart[NGB + 1];
__device__ float d_pool[NGB * HIDD];
__device__ __nv_bfloat16 d_Acat[(size_t)NN * KCAT];           // h split, [N, 2304]
__device__ __nv_bfloat16 d_WcatT[(size_t)NL * HIDD * KCAT];   // W^T split, [L, 768n, 2304k]

// ---------------- CSR build ----------------
__global__ void k_zero_deg() {
    int i = blockIdx.x * 256 + threadIdx.x;
    if (i < NN) d_deg[i] = 0;
}

__global__ void k_hist(const int* __restrict__ ei) {
    int i = blockIdx.x * 256 + threadIdx.x;
    if (i >= EA) return;
    int dst = (i < EE) ? ei[EE + i] : (i - EE);
    atomicAdd(&d_deg[dst], 1);
}

__global__ void k_scan() {
    __shared__ int sdata[1024];
    __shared__ int carry;
    int tid = threadIdx.x;
    if (tid == 0) { carry = 0; d_rowptr[0] = 0; }
    __syncthreads();
    for (int base = 0; base < NN; base += 1024) {
        int i = base + tid;
        int v = (i < NN) ? d_deg[i] : 0;
        sdata[tid] = v;
        __syncthreads();
        for (int off = 1; off < 1024; off <<= 1) {
            int t = (tid >= off) ? sdata[tid - off] : 0;
            __syncthreads();
            sdata[tid] += t;
            __syncthreads();
        }
        int incl = sdata[tid] + carry;
        if (i < NN) d_rowptr[i + 1] = incl;
        __syncthreads();
        if (tid == 1023) carry = incl;
        __syncthreads();
    }
    for (int i = tid; i < NN; i += 1024) d_cursor[i] = d_rowptr[i];
}

__global__ void k_scatter(const int* __restrict__ ei) {
    int i = blockIdx.x * 256 + threadIdx.x;
    if (i >= EA) return;
    int src, dst;
    if (i < EE) { src = ei[i]; dst = ei[EE + i]; }
    else        { src = i - EE; dst = src; }
    int slot = atomicAdd(&d_cursor[dst], 1);
    d_csrsrc[slot] = src;
}

__global__ void k_gstart(const int* __restrict__ batch) {
    int n = blockIdx.x * 256 + threadIdx.x;
    if (n >= NN) return;
    int b = batch[n];
    if (n == 0) {
        for (int bb = 0; bb <= b; bb++) d_gstart[bb] = 0;
    } else {
        int pb = batch[n - 1];
        if (pb != b) for (int bb = pb + 1; bb <= b; bb++) d_gstart[bb] = n;
    }
    if (n == NN - 1) {
        for (int bb = b + 1; bb <= NGB; bb++) d_gstart[bb] = NN;
    }
}

__global__ void k_zero_asd() {
    int i = blockIdx.x * 256 + threadIdx.x;
    if (i < NN * NH) { d_as[i] = 0.f; d_ad[i] = 0.f; }
}

// ---------------- split write helpers ----------------
__device__ __forceinline__ void write_split(int n, int k, float v) {
    __nv_bfloat16 hi = __float2bfloat16(v);
    __nv_bfloat16 lo = __float2bfloat16(v - __bfloat162float(hi));
    size_t base = (size_t)n * KCAT;
    d_Acat[base + k]            = hi;
    d_Acat[base + HIDD + k]     = lo;
    d_Acat[base + 2 * HIDD + k] = hi;
}

__device__ __forceinline__ void write_split4(int n, int j, float4 v) {
    float vv[4] = {v.x, v.y, v.z, v.w};
    __nv_bfloat162 hp[2], lp[2];
#pragma unroll
    for (int q = 0; q < 2; q++) {
        __nv_bfloat16 h0 = __float2bfloat16(vv[2 * q]);
        __nv_bfloat16 h1 = __float2bfloat16(vv[2 * q + 1]);
        __nv_bfloat16 l0 = __float2bfloat16(vv[2 * q]     - __bfloat162float(h0));
        __nv_bfloat16 l1 = __float2bfloat16(vv[2 * q + 1] - __bfloat162float(h1));
        hp[q] = __nv_bfloat162(h0, h1);
        lp[q] = __nv_bfloat162(l0, l1);
    }
    size_t base = (size_t)n * KCAT;
    __nv_bfloat162* p0 = (__nv_bfloat162*)&d_Acat[base + j];
    __nv_bfloat162* p1 = (__nv_bfloat162*)&d_Acat[base + HIDD + j];
    __nv_bfloat162* p2 = (__nv_bfloat162*)&d_Acat[base + 2 * HIDD + j];
    p0[0] = hp[0]; p0[1] = hp[1];
    p1[0] = lp[0]; p1[1] = lp[1];
    p2[0] = hp[0]; p2[1] = hp[1];
}

// ---------------- input projection (split only) ----------------
__global__ void k_proj(const float* __restrict__ x, const float* __restrict__ W,
                       const float* __restrict__ b) {
    int id = blockIdx.x * 256 + threadIdx.x;
    if (id >= NN * HIDD) return;
    int n = id / HIDD, j = id % HIDD;
    float s = b[j];
#pragma unroll
    for (int f = 0; f < 5; f++) s += x[n * 5 + f] * W[f * HIDD + j];
    write_split(n, j, s);
}

// ---------------- bf16 split: weights (once) ----------------
__global__ void k_split_w(const float* __restrict__ convW) {
    int id = blockIdx.x * 256 + threadIdx.x;
    if (id >= NL * HIDD * HIDD) return;
    int l = id / (HIDD * HIDD);
    int rem = id % (HIDD * HIDD);
    int k = rem / HIDD, n = rem % HIDD;
    float v = convW[id];
    __nv_bfloat16 hi = __float2bfloat16(v);
    __nv_bfloat16 lo = __float2bfloat16(v - __bfloat162float(hi));
    size_t base = ((size_t)l * HIDD + n) * KCAT;
    d_WcatT[base + k]            = hi;
    d_WcatT[base + HIDD + k]     = hi;
    d_WcatT[base + 2 * HIDD + k] = lo;
}

// =====================================================================
// HMMA GEMM: 128x256 tile, BK=64, 4-stage cp.async, mma.m16n8k16.bf16
// Fused epilogue: d_g store + att_src/att_dst dot products (atomicAdd)
// =====================================================================
#define BK 64
#define STAGES 4
#define STG_A 16384
#define STG_B 32768
#define SMEM_GEMM (STAGES * (STG_A + STG_B))   // 196608

__device__ __forceinline__ uint32_t swz(uint32_t b) { return b ^ ((b >> 3) & 0x70); }

__device__ __forceinline__ uint32_t smem_u32(const void* p) {
    uint32_t a;
    asm("{ .reg .u64 t; cvta.to.shared.u64 t, %1; cvt.u32.u64 %0, t; }" : "=r"(a) : "l"(p));
    return a;
}

#define CP_ASYNC(dst, src, sz) \
    asm volatile("cp.async.cg.shared.global [%0], [%1], 16, %2;" \
        :: "r"(dst), "l"(src), "r"(sz))
#define CP_COMMIT() asm volatile("cp.async.commit_group;")
#define CP_WAIT2()  asm volatile("cp.async.wait_group 2;")

#define LDMX4(r0, r1, r2, r3, a) \
    asm volatile("ldmatrix.sync.aligned.m8n8.x4.shared.b16 {%0,%1,%2,%3}, [%4];" \
        : "=r"(r0), "=r"(r1), "=r"(r2), "=r"(r3) : "r"(a))

#define MMA16816(d, a, b) \
    asm volatile("mma.sync.aligned.m16n8k16.row.col.f32.bf16.bf16.f32 " \
        "{%0,%1,%2,%3}, {%4,%5,%6,%7}, {%8,%9}, {%0,%1,%2,%3};" \
        : "+f"((d)[0]), "+f"((d)[1]), "+f"((d)[2]), "+f"((d)[3]) \
        : "r"((a)[0]), "r"((a)[1]), "r"((a)[2]), "r"((a)[3]), "r"((b)[0]), "r"((b)[1]))

__global__ __launch_bounds__(256, 1) void k_gemm_hmma(
    const __nv_bfloat16* __restrict__ Wl,
    const float* __restrict__ attS, const float* __restrict__ attD)
{
    extern __shared__ __align__(128) char smem[];
    uint32_t sA = smem_u32(smem);
    uint32_t sB = sA + STAGES * STG_A;

    const int tid = threadIdx.x;
    const int lane = tid & 31, warp = tid >> 5;
    const int wm = warp & 3, wn = warp >> 2;
    const int mtile = blockIdx.y, ntile = blockIdx.x;
    const int mbase = mtile * 128;
    const int nbase = ntile * 256;

    const __nv_bfloat16* Ag = d_Acat;

    auto issue_stage = [&](int kt, int st) {
        int k0 = kt * BK;
        uint32_t a_dst = sA + st * STG_A;
#pragma unroll
        for (int it = 0; it < 4; it++) {
            int id = it * 256 + tid;
            int row = id >> 3, ck = id & 7;
            int gr = mbase + row;
            const __nv_bfloat16* srcA = Ag + (size_t)gr * KCAT + k0 + ck * 8;
            CP_ASYNC(a_dst + swz(row * 128 + ck * 16), srcA, (gr < NN) ? 16 : 0);
        }
        uint32_t b_dst = sB + st * STG_B;
#pragma unroll
        for (int it = 0; it < 8; it++) {
            int id = it * 256 + tid;
            int row = id >> 3, ck = id & 7;
            const __nv_bfloat16* srcB = Wl + (size_t)(nbase + row) * KCAT + k0 + ck * 8;
            CP_ASYNC(b_dst + swz(row * 128 + ck * 16), srcB, 16);
        }
        CP_COMMIT();
    };

    issue_stage(0, 0);
    issue_stage(1, 1);
    issue_stage(2, 2);

    float acc[2][16][4];
#pragma unroll
    for (int i = 0; i < 2; i++)
#pragma unroll
        for (int j = 0; j < 16; j++)
#pragma unroll
            for (int c = 0; c < 4; c++) acc[i][j][c] = 0.f;

    const int NKT = KCAT / BK;
    for (int kt = 0; kt < NKT; kt++) {
        CP_WAIT2();
        __syncthreads();
        if (kt + 3 < NKT) issue_stage(kt + 3, (kt + 3) % STAGES);
        else CP_COMMIT();

        int st = kt % STAGES;
        uint32_t aS = sA + st * STG_A;
        uint32_t bS = sB + st * STG_B;

#pragma unroll
        for (int ks = 0; ks < 4; ks++) {
            uint32_t afr[2][4];
#pragma unroll
            for (int im = 0; im < 2; im++) {
                int row = wm * 32 + im * 16 + (lane & 15);
                int kk = ks * 16 + (lane >> 4) * 8;
                LDMX4(afr[im][0], afr[im][1], afr[im][2], afr[im][3],
                      aS + swz(row * 128 + kk * 2));
            }
#pragma unroll
            for (int half = 0; half < 2; half++) {
                uint32_t bfr[8][2];
#pragma unroll
                for (int pr = 0; pr < 4; pr++) {
                    int nrow = wn * 128 + half * 64 + pr * 16 + (lane & 7) + ((lane & 16) ? 8 : 0);
                    int kk = ks * 16 + ((lane & 8) ? 8 : 0);
                    uint32_t r0, r1, r2, r3;
                    LDMX4(r0, r1, r2, r3, bS + swz(nrow * 128 + kk * 2));
                    bfr[pr * 2][0] = r0;     bfr[pr * 2][1] = r1;
                    bfr[pr * 2 + 1][0] = r2; bfr[pr * 2 + 1][1] = r3;
                }
#pragma unroll
                for (int im = 0; im < 2; im++)
#pragma unroll
                    for (int jn = 0; jn < 8; jn++)
                        MMA16816(acc[im][half * 8 + jn], afr[im], bfr[jn]);
            }
        }
        __syncthreads();
    }

    // ---------------- fused epilogue ----------------
    const int base0 = nbase + wn * 128;
    const int hA = base0 / 96;
    float ps[2][2][2];
    float pd[2][2][2];
#pragma unroll
    for (int a = 0; a < 2; a++)
#pragma unroll
        for (int b = 0; b < 2; b++)
#pragma unroll
            for (int c = 0; c < 2; c++) { ps[a][b][c] = 0.f; pd[a][b][c] = 0.f; }

#pragma unroll
    for (int jn = 0; jn < 16; jn++) {
        int col = base0 + jn * 8 + (lane & 3) * 2;
        int slot = (col / 96) - hA;
        float as0 = __ldg(attS + col), as1 = __ldg(attS + col + 1);
        float ad0 = __ldg(attD + col), ad1 = __ldg(attD + col + 1);
#pragma unroll
        for (int im = 0; im < 2; im++) {
            int r0 = mbase + wm * 32 + im * 16 + (lane >> 2);
            if (r0 < NN)
                *(float2*)&d_g[(size_t)r0 * HIDD + col] =
                    make_float2(acc[im][jn][0], acc[im][jn][1]);
            if (r0 + 8 < NN)
                *(float2*)&d_g[(size_t)(r0 + 8) * HIDD + col] =
                    make_float2(acc[im][jn][2], acc[im][jn][3]);
            ps[im][0][slot] += acc[im][jn][0] * as0 + acc[im][jn][1] * as1;
            pd[im][0][slot] += acc[im][jn][0] * ad0 + acc[im][jn][1] * ad1;
            ps[im][1][slot] += acc[im][jn][2] * as0 + acc[im][jn][3] * as1;
            pd[im][1][slot] += acc[im][jn][2] * ad0 + acc[im][jn][3] * ad1;
        }
    }
#pragma unroll
    for (int im = 0; im < 2; im++)
#pragma unroll
        for (int rh = 0; rh < 2; rh++)
#pragma unroll
            for (int sl = 0; sl < 2; sl++) {
                float vs = ps[im][rh][sl], vd = pd[im][rh][sl];
                vs += __shfl_xor_sync(0xffffffffu, vs, 1);
                vs += __shfl_xor_sync(0xffffffffu, vs, 2);
                vd += __shfl_xor_sync(0xffffffffu, vd, 1);
                vd += __shfl_xor_sync(0xffffffffu, vd, 2);
                if ((lane & 3) == 0) {
                    int row = mbase + wm * 32 + im * 16 + (lane >> 2) + rh * 8;
                    int h = hA + sl;
                    if (row < NN && h < NH) {
                        atomicAdd(&d_as[row * 8 + h], vs);
                        atomicAdd(&d_ad[row * 8 + h], vd);
                    }
                }
            }
}

// =====================================================================
// Attention: 2 warps per node (64 lanes softmax, split-channel gather)
// block = 256 threads = 4 nodes. All __syncthreads unconditional.
// =====================================================================
__global__ __launch_bounds__(256) void k_attn(const float* __restrict__ bias, int write_h) {
    __shared__ float ebuf[4][MAXD * 8];    // 8 KB: unnormalized p per edge/head
    __shared__ float redm[4][2][8];        // cross-warp max exchange
    __shared__ float reds[4][2][8];        // cross-warp sum exchange

    const int tid = threadIdx.x;
    const int lane = tid & 31;
    const int pw = (tid >> 5) & 1;         // warp within pair
    const int node = tid >> 6;             // 0..3
    const int lg = tid & 63;               // lane within pair
    const int n = blockIdx.x * 4 + node;

    const int beg = d_rowptr[n], end = d_rowptr[n + 1];
    const int deg = end - beg;

    const float4* adp = (const float4*)(d_ad + n * 8);
    float4 ad0 = adp[0], ad1 = adp[1];
    float ad[8] = {ad0.x, ad0.y, ad0.z, ad0.w, ad1.x, ad1.y, ad1.z, ad1.w};

    // ---- pass 1: running max over this lane's edges ----
    float mx[8];
#pragma unroll
    for (int h = 0; h < 8; h++) mx[h] = -1e30f;
    for (int i0 = lg; i0 < deg; i0 += 64) {
        int s = d_csrsrc[beg + i0];
        const float4* ap = (const float4*)(d_as + s * 8);
        float4 a0 = ap[0], a1 = ap[1];
        float ev[8] = {a0.x, a0.y, a0.z, a0.w, a1.x, a1.y, a1.z, a1.w};
#pragma unroll
        for (int h = 0; h < 8; h++) {
            float e = ev[h] + ad[h];
            e = e > 0.f ? e : 0.2f * e;
            mx[h] = fmaxf(mx[h], e);
        }
    }
#pragma unroll
    for (int h = 0; h < 8; h++)
        for (int off = 16; off; off >>= 1)
            mx[h] = fmaxf(mx[h], __shfl_xor_sync(0xffffffffu, mx[h], off));
    if (lane == 0) {
#pragma unroll
        for (int h = 0; h < 8; h++) redm[node][pw][h] = mx[h];
    }
    __syncthreads();
#pragma unroll
    for (int h = 0; h < 8; h++) mx[h] = fmaxf(redm[node][0][h], redm[node][1][h]);

    // ---- pass 2: exp + sum (cache p in ebuf when deg fits) ----
    float sm[8];
#pragma unroll
    for (int h = 0; h < 8; h++) sm[h] = 0.f;
    for (int i0 = lg; i0 < deg; i0 += 64) {
        int s = d_csrsrc[beg + i0];
        const float4* ap = (const float4*)(d_as + s * 8);
        float4 a0 = ap[0], a1 = ap[1];
        float ev[8] = {a0.x, a0.y, a0.z, a0.w, a1.x, a1.y, a1.z, a1.w};
#pragma unroll
        for (int h = 0; h < 8; h++) {
            float e = ev[h] + ad[h];
            e = e > 0.f ? e : 0.2f * e;
            float p = __expf(e - mx[h]);
            if (deg <= MAXD) ebuf[node][i0 * 8 + h] = p;
            sm[h] += p;
        }
    }
#pragma unroll
    for (int h = 0; h < 8; h++)
        for (int off = 16; off; off >>= 1)
            sm[h] += __shfl_xor_sync(0xffffffffu, sm[h], off);
    if (lane == 0) {
#pragma unroll
        for (int h = 0; h < 8; h++) reds[node][pw][h] = sm[h];
    }
    __syncthreads();    // covers reds AND ebuf writes
    float inv[8];
#pragma unroll
    for (int h = 0; h < 8; h++)
        inv[h] = 1.f / (reds[node][0][h] + reds[node][1][h] + 1e-16f);

    // ---- gather: this warp covers float4 slots 3*pw..3*pw+2 ----
    float4 acc4[3];
#pragma unroll
    for (int t = 0; t < 3; t++) acc4[t] = make_float4(0.f, 0.f, 0.f, 0.f);
    int j4_t[3], head_t[3];
#pragma unroll
    for (int t = 0; t < 3; t++) {
        j4_t[t] = lane + 32 * (3 * pw + t);
        head_t[t] = j4_t[t] / 24;
    }

    if (deg <= MAXD) {
        float invt[3];
#pragma unroll
        for (int t = 0; t < 3; t++) invt[t] = inv[head_t[t]];
        int le = 0;
        for (; le + 4 <= deg; le += 4) {
            int s0 = d_csrsrc[beg + le];
            int s1 = d_csrsrc[beg + le + 1];
            int s2 = d_csrsrc[beg + le + 2];
            int s3 = d_csrsrc[beg + le + 3];
            const float4* g0 = (const float4*)(d_g + (size_t)s0 * HIDD);
            const float4* g1 = (const float4*)(d_g + (size_t)s1 * HIDD);
            const float4* g2 = (const float4*)(d_g + (size_t)s2 * HIDD);
            const float4* g3 = (const float4*)(d_g + (size_t)s3 * HIDD);
#pragma unroll
            for (int t = 0; t < 3; t++) {
                int j4 = j4_t[t];
                float a0 = ebuf[node][le * 8 + head_t[t]] * invt[t];
                float a1 = ebuf[node][(le + 1) * 8 + head_t[t]] * invt[t];
                float a2 = ebuf[node][(le + 2) * 8 + head_t[t]] * invt[t];
                float a3 = ebuf[node][(le + 3) * 8 + head_t[t]] * invt[t];
                float4 v0 = g0[j4], v1 = g1[j4], v2 = g2[j4], v3 = g3[j4];
                acc4[t].x += a0 * v0.x + a1 * v1.x + a2 * v2.x + a3 * v3.x;
                acc4[t].y += a0 * v0.y + a1 * v1.y + a2 * v2.y + a3 * v3.y;
                acc4[t].z += a0 * v0.z + a1 * v1.z + a2 * v2.z + a3 * v3.z;
                acc4[t].w += a0 * v0.w + a1 * v1.w + a2 * v2.w + a3 * v3.w;
            }
        }
        for (; le < deg; le++) {
            int s0 = d_csrsrc[beg + le];
            const float4* g0 = (const float4*)(d_g + (size_t)s0 * HIDD);
#pragma unroll
            for (int t = 0; t < 3; t++) {
                int j4 = j4_t[t];
                float a0 = ebuf[node][le * 8 + head_t[t]] * invt[t];
                float4 v0 = g0[j4];
                acc4[t].x += a0 * v0.x;
                acc4[t].y += a0 * v0.y;
                acc4[t].z += a0 * v0.z;
                acc4[t].w += a0 * v0.w;
            }
        }
    } else {
        // rare: recompute alpha per edge (no syncs here)
        for (int le = 0; le < deg; le++) {
            int s0 = d_csrsrc[beg + le];
            const float4* g0 = (const float4*)(d_g + (size_t)s0 * HIDD);
#pragma unroll
            for (int t = 0; t < 3; t++) {
                int h = head_t[t];
                float e = d_as[s0 * 8 + h] + ad[h];
                e = e > 0.f ? e : 0.2f * e;
                float a0 = __expf(e - mx[h]) * inv[h];
                float4 v0 = g0[j4_t[t]];
                acc4[t].x += a0 * v0.x;
                acc4[t].y += a0 * v0.y;
                acc4[t].z += a0 * v0.z;
                acc4[t].w += a0 * v0.w;
            }
        }
    }

    // ---- epilogue: bias + relu, write split (and h on last layer) ----
#pragma unroll
    for (int t = 0; t < 3; t++) {
        int j = 4 * j4_t[t];
        float4 b4 = *(const float4*)(bias + j);
        float4 v = acc4[t];
        v.x = fmaxf(v.x + b4.x, 0.f);
        v.y = fmaxf(v.y + b4.y, 0.f);
        v.z = fmaxf(v.z + b4.z, 0.f);
        v.w = fmaxf(v.w + b4.w, 0.f);
        if (write_h) *(float4*)&d_h[(size_t)n * HIDD + j] = v;
        write_split4(n, j, v);
    }
}

// ---------------- pooling / fc ----------------
__global__ void k_pool() {
    int b = blockIdx.x;
    int j = blockIdx.y * 256 + threadIdx.x;
    int beg = d_gstart[b], end = d_gstart[b + 1];
    float s = 0.f;
    for (int n = beg; n < end; n++) s += d_h[(size_t)n * HIDD + j];
    float cnt = (float)(end - beg);
    d_pool[b * HIDD + j] = s / fmaxf(cnt, 1.0f);
}

__global__ void k_fc(const float* __restrict__ W, const float* __restrict__ b,
                     float* __restrict__ out) {
    int id = blockIdx.x * 256 + threadIdx.x;
    if (id >= NGB * EMB) return;
    int bb = id / EMB, k = id % EMB;
    float s = b[k];
    for (int j = 0; j < HIDD; j++) s += d_pool[bb * HIDD + j] * W[j * EMB + k];
    out[id] = s;
}

// ---------------- host launch ----------------
extern "C" void kernel_launch(void* const* d_in, const int* in_sizes, int n_in,
                              void* d_out, int out_size) {
    const float* x     = (const float*)d_in[0];
    const int*   ei    = (const int*)d_in[1];
    const int*   batch = (const int*)d_in[2];
    const float* projW = (const float*)d_in[3];
    const float* projb = (const float*)d_in[4];
    const float* convW = (const float*)d_in[5];
    const float* attS  = (const float*)d_in[6];
    const float* attD  = (const float*)d_in[7];
    const float* convb = (const float*)d_in[8];
    const float* fcW   = (const float*)d_in[9];
    const float* fcb   = (const float*)d_in[10];
    float* out = (float*)d_out;

    static bool attr_set = false;
    if (!attr_set) {
        cudaFuncSetAttribute(k_gemm_hmma, cudaFuncAttributeMaxDynamicSharedMemorySize, SMEM_GEMM);
        attr_set = true;
    }

    void* pW = nullptr;
    cudaGetSymbolAddress(&pW, d_WcatT);
    const __nv_bfloat16* Wcat = (const __nv_bfloat16*)pW;

    k_zero_deg<<<(NN + 255) / 256, 256>>>();
    k_hist<<<(EA + 255) / 256, 256>>>(ei);
    k_scan<<<1, 1024>>>();
    k_scatter<<<(EA + 255) / 256, 256>>>(ei);
    k_gstart<<<(NN + 255) / 256, 256>>>(batch);
    k_proj<<<(NN * HIDD + 255) / 256, 256>>>(x, projW, projb);
    k_split_w<<<(NL * HIDD * HIDD + 255) / 256, 256>>>(convW);
    k_zero_asd<<<(NN * NH + 255) / 256, 256>>>();

    for (int l = 0; l < NL; l++) {
        dim3 gg(HIDD / 256, (NN + 127) / 128);   // 3 x 157
        k_gemm_hmma<<<gg, 256, SMEM_GEMM>>>(Wcat + (size_t)l * HIDD * KCAT,
                                            attS + l * HIDD, attD + l * HIDD);
        k_attn<<<NN / 4, 256>>>(convb + l * HIDD, (l == NL - 1) ? 1 : 0);
        if (l != NL - 1) k_zero_asd<<<(NN * NH + 255) / 256, 256>>>();
    }

    dim3 gp(NGB, 3);
    k_pool<<<gp, 256>>>();
    k_fc<<<(NGB * EMB + 255) / 256, 256>>>(fcW, fcb, out);
}

// round 10
// speedup vs baseline: 1.0360x; 1.0360x over previous
#include <cuda_runtime.h>
#include <cuda_bf16.h>
#include <cstdint>

#define NN 20000
#define EE 320000
#define EA 340000      // E + N self loops
#define HIDD 768
#define NH 8
#define NC 96
#define NL 16
#define NGB 16
#define EMB 512
#define KCAT 2304      // 3 * HIDD (bf16 split: hi*hi + lo*hi + hi*lo)
#define MAXD 64        // smem softmax path cap (fallback to global beyond)

// ---------------- scratch (device globals; no allocations) ----------------
__device__ float d_h[NN * HIDD];
__device__ float d_g[NN * HIDD];
__device__ float d_as[NN * NH];
__device__ float d_ad[NN * NH];
__device__ float d_e[EA * NH];          // fallback path only
__device__ int   d_deg[NN];
__device__ int   d_rowptr[NN + 1];
__device__ int   d_cursor[NN];
__device__ int   d_csrsrc[EA];
__device__ int   d_gstart[NGB + 1];
__device__ float d_pool[NGB * HIDD];
__device__ __nv_bfloat16 d_Acat[(size_t)NN * KCAT];           // h split, [N, 2304]
__device__ __nv_bfloat16 d_WcatT[(size_t)NL * HIDD * KCAT];   // W^T split, [L, 768n, 2304k]

// ---------------- CSR build ----------------
__global__ void k_zero_deg() {
    int i = blockIdx.x * 256 + threadIdx.x;
    if (i < NN) d_deg[i] = 0;
}

__global__ void k_hist(const int* __restrict__ ei) {
    int i = blockIdx.x * 256 + threadIdx.x;
    if (i >= EA) return;
    int dst = (i < EE) ? ei[EE + i] : (i - EE);
    atomicAdd(&d_deg[dst], 1);
}

__global__ void k_scan() {
    __shared__ int sdata[1024];
    __shared__ int carry;
    int tid = threadIdx.x;
    if (tid == 0) { carry = 0; d_rowptr[0] = 0; }
    __syncthreads();
    for (int base = 0; base < NN; base += 1024) {
        int i = base + tid;
        int v = (i < NN) ? d_deg[i] : 0;
        sdata[tid] = v;
        __syncthreads();
        for (int off = 1; off < 1024; off <<= 1) {
            int t = (tid >= off) ? sdata[tid - off] : 0;
            __syncthreads();
            sdata[tid] += t;
            __syncthreads();
        }
        int incl = sdata[tid] + carry;
        if (i < NN) d_rowptr[i + 1] = incl;
        __syncthreads();
        if (tid == 1023) carry = incl;
        __syncthreads();
    }
    for (int i = tid; i < NN; i += 1024) d_cursor[i] = d_rowptr[i];
}

__global__ void k_scatter(const int* __restrict__ ei) {
    int i = blockIdx.x * 256 + threadIdx.x;
    if (i >= EA) return;
    int src, dst;
    if (i < EE) { src = ei[i]; dst = ei[EE + i]; }
    else        { src = i - EE; dst = src; }
    int slot = atomicAdd(&d_cursor[dst], 1);
    d_csrsrc[slot] = src;
}

__global__ void k_gstart(const int* __restrict__ batch) {
    int n = blockIdx.x * 256 + threadIdx.x;
    if (n >= NN) return;
    int b = batch[n];
    if (n == 0) {
        for (int bb = 0; bb <= b; bb++) d_gstart[bb] = 0;
    } else {
        int pb = batch[n - 1];
        if (pb != b) for (int bb = pb + 1; bb <= b; bb++) d_gstart[bb] = n;
    }
    if (n == NN - 1) {
        for (int bb = b + 1; bb <= NGB; bb++) d_gstart[bb] = NN;
    }
}

__global__ void k_zero_asd() {
    int i = blockIdx.x * 256 + threadIdx.x;
    if (i < NN * NH) { d_as[i] = 0.f; d_ad[i] = 0.f; }
}

// ---------------- split write helpers ----------------
__device__ __forceinline__ void write_split(int n, int k, float v) {
    __nv_bfloat16 hi = __float2bfloat16(v);
    __nv_bfloat16 lo = __float2bfloat16(v - __bfloat162float(hi));
    size_t base = (size_t)n * KCAT;
    d_Acat[base + k]            = hi;
    d_Acat[base + HIDD + k]     = lo;
    d_Acat[base + 2 * HIDD + k] = hi;
}

__device__ __forceinline__ void write_split4(int n, int j, float4 v) {
    float vv[4] = {v.x, v.y, v.z, v.w};
    __nv_bfloat162 hp[2], lp[2];
#pragma unroll
    for (int q = 0; q < 2; q++) {
        __nv_bfloat16 h0 = __float2bfloat16(vv[2 * q]);
        __nv_bfloat16 h1 = __float2bfloat16(vv[2 * q + 1]);
        __nv_bfloat16 l0 = __float2bfloat16(vv[2 * q]     - __bfloat162float(h0));
        __nv_bfloat16 l1 = __float2bfloat16(vv[2 * q + 1] - __bfloat162float(h1));
        hp[q] = __nv_bfloat162(h0, h1);
        lp[q] = __nv_bfloat162(l0, l1);
    }
    size_t base = (size_t)n * KCAT;
    __nv_bfloat162* p0 = (__nv_bfloat162*)&d_Acat[base + j];
    __nv_bfloat162* p1 = (__nv_bfloat162*)&d_Acat[base + HIDD + j];
    __nv_bfloat162* p2 = (__nv_bfloat162*)&d_Acat[base + 2 * HIDD + j];
    p0[0] = hp[0]; p0[1] = hp[1];
    p1[0] = lp[0]; p1[1] = lp[1];
    p2[0] = hp[0]; p2[1] = hp[1];
}

// ---------------- input projection (split only) ----------------
__global__ void k_proj(const float* __restrict__ x, const float* __restrict__ W,
                       const float* __restrict__ b) {
    int id = blockIdx.x * 256 + threadIdx.x;
    if (id >= NN * HIDD) return;
    int n = id / HIDD, j = id % HIDD;
    float s = b[j];
#pragma unroll
    for (int f = 0; f < 5; f++) s += x[n * 5 + f] * W[f * HIDD + j];
    write_split(n, j, s);
}

// ---------------- bf16 split: weights (once) ----------------
__global__ void k_split_w(const float* __restrict__ convW) {
    int id = blockIdx.x * 256 + threadIdx.x;
    if (id >= NL * HIDD * HIDD) return;
    int l = id / (HIDD * HIDD);
    int rem = id % (HIDD * HIDD);
    int k = rem / HIDD, n = rem % HIDD;
    float v = convW[id];
    __nv_bfloat16 hi = __float2bfloat16(v);
    __nv_bfloat16 lo = __float2bfloat16(v - __bfloat162float(hi));
    size_t base = ((size_t)l * HIDD + n) * KCAT;
    d_WcatT[base + k]            = hi;
    d_WcatT[base + HIDD + k]     = hi;
    d_WcatT[base + 2 * HIDD + k] = lo;
}

// =====================================================================
// HMMA GEMM: 128x256 CTA tile, 64x64 warp tile (2m x 4n warps), BK=64,
// 4-stage cp.async, mma.m16n8k16.bf16, fused asd epilogue
// =====================================================================
#define BK 64
#define STAGES 4
#define STG_A 16384
#define STG_B 32768
#define SMEM_GEMM (STAGES * (STG_A + STG_B))   // 196608

__device__ __forceinline__ uint32_t swz(uint32_t b) { return b ^ ((b >> 3) & 0x70); }

__device__ __forceinline__ uint32_t smem_u32(const void* p) {
    uint32_t a;
    asm("{ .reg .u64 t; cvta.to.shared.u64 t, %1; cvt.u32.u64 %0, t; }" : "=r"(a) : "l"(p));
    return a;
}

#define CP_ASYNC(dst, src, sz) \
    asm volatile("cp.async.cg.shared.global [%0], [%1], 16, %2;" \
        :: "r"(dst), "l"(src), "r"(sz))
#define CP_COMMIT() asm volatile("cp.async.commit_group;")
#define CP_WAIT2()  asm volatile("cp.async.wait_group 2;")

#define LDMX4(r0, r1, r2, r3, a) \
    asm volatile("ldmatrix.sync.aligned.m8n8.x4.shared.b16 {%0,%1,%2,%3}, [%4];" \
        : "=r"(r0), "=r"(r1), "=r"(r2), "=r"(r3) : "r"(a))

#define MMA16816(d, a, b) \
    asm volatile("mma.sync.aligned.m16n8k16.row.col.f32.bf16.bf16.f32 " \
        "{%0,%1,%2,%3}, {%4,%5,%6,%7}, {%8,%9}, {%0,%1,%2,%3};" \
        : "+f"((d)[0]), "+f"((d)[1]), "+f"((d)[2]), "+f"((d)[3]) \
        : "r"((a)[0]), "r"((a)[1]), "r"((a)[2]), "r"((a)[3]), "r"((b)[0]), "r"((b)[1]))

__global__ __launch_bounds__(256, 1) void k_gemm_hmma(
    const __nv_bfloat16* __restrict__ Wl,
    const float* __restrict__ attS, const float* __restrict__ attD)
{
    extern __shared__ __align__(128) char smem[];
    uint32_t sA = smem_u32(smem);
    uint32_t sB = sA + STAGES * STG_A;

    const int tid = threadIdx.x;
    const int lane = tid & 31, warp = tid >> 5;
    const int wm = warp & 1, wn = warp >> 1;         // 2 m-warps x 4 n-warps
    const int mtile = blockIdx.y, ntile = blockIdx.x;
    const int mbase = mtile * 128;
    const int nbase = ntile * 256;

    const __nv_bfloat16* Ag = d_Acat;

    auto issue_stage = [&](int kt, int st) {
        int k0 = kt * BK;
        uint32_t a_dst = sA + st * STG_A;
#pragma unroll
        for (int it = 0; it < 4; it++) {
            int id = it * 256 + tid;
            int row = id >> 3, ck = id & 7;
            int gr = mbase + row;
            const __nv_bfloat16* srcA = Ag + (size_t)gr * KCAT + k0 + ck * 8;
            CP_ASYNC(a_dst + swz(row * 128 + ck * 16), srcA, (gr < NN) ? 16 : 0);
        }
        uint32_t b_dst = sB + st * STG_B;
#pragma unroll
        for (int it = 0; it < 8; it++) {
            int id = it * 256 + tid;
            int row = id >> 3, ck = id & 7;
            const __nv_bfloat16* srcB = Wl + (size_t)(nbase + row) * KCAT + k0 + ck * 8;
            CP_ASYNC(b_dst + swz(row * 128 + ck * 16), srcB, 16);
        }
        CP_COMMIT();
    };

    issue_stage(0, 0);
    issue_stage(1, 1);
    issue_stage(2, 2);

    float acc[4][8][4];
#pragma unroll
    for (int i = 0; i < 4; i++)
#pragma unroll
        for (int j = 0; j < 8; j++)
#pragma unroll
            for (int c = 0; c < 4; c++) acc[i][j][c] = 0.f;

    const int NKT = KCAT / BK;
    for (int kt = 0; kt < NKT; kt++) {
        CP_WAIT2();
        __syncthreads();
        if (kt + 3 < NKT) issue_stage(kt + 3, (kt + 3) % STAGES);
        else CP_COMMIT();

        int st = kt % STAGES;
        uint32_t aS = sA + st * STG_A;
        uint32_t bS = sB + st * STG_B;

#pragma unroll
        for (int ks = 0; ks < 4; ks++) {
            uint32_t afr[4][4];
#pragma unroll
            for (int im = 0; im < 4; im++) {
                int row = wm * 64 + im * 16 + (lane & 15);
                int kk = ks * 16 + (lane >> 4) * 8;
                LDMX4(afr[im][0], afr[im][1], afr[im][2], afr[im][3],
                      aS + swz(row * 128 + kk * 2));
            }
            uint32_t bfr[8][2];
#pragma unroll
            for (int pr = 0; pr < 4; pr++) {
                int nrow = wn * 64 + pr * 16 + (lane & 7) + ((lane & 16) ? 8 : 0);
                int kk = ks * 16 + ((lane & 8) ? 8 : 0);
                uint32_t r0, r1, r2, r3;
                LDMX4(r0, r1, r2, r3, bS + swz(nrow * 128 + kk * 2));
                bfr[pr * 2][0] = r0;     bfr[pr * 2][1] = r1;
                bfr[pr * 2 + 1][0] = r2; bfr[pr * 2 + 1][1] = r3;
            }
#pragma unroll
            for (int im = 0; im < 4; im++)
#pragma unroll
                for (int jn = 0; jn < 8; jn++)
                    MMA16816(acc[im][jn], afr[im], bfr[jn]);
        }
        __syncthreads();
    }

    // ---------------- fused epilogue ----------------
    const int base0 = nbase + wn * 64;
    const int hA = base0 / 96;          // 64-col segment spans heads hA..hA+1
    float ps[4][2][2];                  // [im][rowhalf][slot]
    float pd[4][2][2];
#pragma unroll
    for (int a = 0; a < 4; a++)
#pragma unroll
        for (int b = 0; b < 2; b++)
#pragma unroll
            for (int c = 0; c < 2; c++) { ps[a][b][c] = 0.f; pd[a][b][c] = 0.f; }

#pragma unroll
    for (int jn = 0; jn < 8; jn++) {
        int col = base0 + jn * 8 + (lane & 3) * 2;
        int slot = (col / 96) - hA;
        float as0 = __ldg(attS + col), as1 = __ldg(attS + col + 1);
        float ad0 = __ldg(attD + col), ad1 = __ldg(attD + col + 1);
#pragma unroll
        for (int im = 0; im < 4; im++) {
            int r0 = mbase + wm * 64 + im * 16 + (lane >> 2);
            if (r0 < NN)
                *(float2*)&d_g[(size_t)r0 * HIDD + col] =
                    make_float2(acc[im][jn][0], acc[im][jn][1]);
            if (r0 + 8 < NN)
                *(float2*)&d_g[(size_t)(r0 + 8) * HIDD + col] =
                    make_float2(acc[im][jn][2], acc[im][jn][3]);
            ps[im][0][slot] += acc[im][jn][0] * as0 + acc[im][jn][1] * as1;
            pd[im][0][slot] += acc[im][jn][0] * ad0 + acc[im][jn][1] * ad1;
            ps[im][1][slot] += acc[im][jn][2] * as0 + acc[im][jn][3] * as1;
            pd[im][1][slot] += acc[im][jn][2] * ad0 + acc[im][jn][3] * ad1;
        }
    }
#pragma unroll
    for (int im = 0; im < 4; im++)
#pragma unroll
        for (int rh = 0; rh < 2; rh++)
#pragma unroll
            for (int sl = 0; sl < 2; sl++) {
                float vs = ps[im][rh][sl], vd = pd[im][rh][sl];
                vs += __shfl_xor_sync(0xffffffffu, vs, 1);
                vs += __shfl_xor_sync(0xffffffffu, vs, 2);
                vd += __shfl_xor_sync(0xffffffffu, vd, 1);
                vd += __shfl_xor_sync(0xffffffffu, vd, 2);
                if ((lane & 3) == 0) {
                    int row = mbase + wm * 64 + im * 16 + (lane >> 2) + rh * 8;
                    int h = hA + sl;
                    if (row < NN && h < NH) {
                        atomicAdd(&d_as[row * 8 + h], vs);
                        atomicAdd(&d_ad[row * 8 + h], vd);
                    }
                }
            }
}

// ---------------- per-node softmax + aggregate (R8 version) ----------------
__global__ __launch_bounds__(256) void k_attn(const float* __restrict__ bias, int write_h) {
    __shared__ float ebuf[8][MAXD * 8];
    __shared__ float s_alpha[8][8];

    int warp = threadIdx.x >> 5, lane = threadIdx.x & 31;
    int n = blockIdx.x * 8 + warp;

    int beg = d_rowptr[n], end = d_rowptr[n + 1];
    int deg = end - beg;

    const float4* adp = (const float4*)(d_ad + n * 8);
    float4 ad0 = adp[0], ad1 = adp[1];
    float ad[8] = {ad0.x, ad0.y, ad0.z, ad0.w, ad1.x, ad1.y, ad1.z, ad1.w};

    float4 acc4[6];
#pragma unroll
    for (int t = 0; t < 6; t++) acc4[t] = make_float4(0.f, 0.f, 0.f, 0.f);

    int head_t[6];
#pragma unroll
    for (int t = 0; t < 6; t++) head_t[t] = (lane + 32 * t) / 24;

    if (deg <= MAXD) {
        float mx[8];
#pragma unroll
        for (int h = 0; h < 8; h++) mx[h] = -1e30f;
#pragma unroll
        for (int it = 0; it < 2; it++) {
            int le = it * 32 + lane;
            if (le < deg) {
                int s = d_csrsrc[beg + le];
                const float4* ap = (const float4*)(d_as + s * 8);
                float4 a0 = ap[0], a1 = ap[1];
                float ev[8] = {a0.x, a0.y, a0.z, a0.w, a1.x, a1.y, a1.z, a1.w};
#pragma unroll
                for (int h = 0; h < 8; h++) {
                    float e = ev[h] + ad[h];
                    e = e > 0.f ? e : 0.2f * e;
                    ebuf[warp][le * 8 + h] = e;
                    mx[h] = fmaxf(mx[h], e);
                }
            }
        }
#pragma unroll
        for (int h = 0; h < 8; h++)
            for (int off = 16; off; off >>= 1)
                mx[h] = fmaxf(mx[h], __shfl_xor_sync(0xffffffffu, mx[h], off));
        __syncwarp();

        float sm[8];
#pragma unroll
        for (int h = 0; h < 8; h++) sm[h] = 0.f;
#pragma unroll
        for (int it = 0; it < 2; it++) {
            int le = it * 32 + lane;
            if (le < deg) {
#pragma unroll
                for (int h = 0; h < 8; h++) {
                    float p = __expf(ebuf[warp][le * 8 + h] - mx[h]);
                    ebuf[warp][le * 8 + h] = p;
                    sm[h] += p;
                }
            }
        }
#pragma unroll
        for (int h = 0; h < 8; h++)
            for (int off = 16; off; off >>= 1)
                sm[h] += __shfl_xor_sync(0xffffffffu, sm[h], off);
        float inv[8];
#pragma unroll
        for (int h = 0; h < 8; h++) inv[h] = 1.f / (sm[h] + 1e-16f);
        __syncwarp();

#pragma unroll
        for (int it = 0; it < 2; it++) {
            int le = it * 32 + lane;
            if (le < deg) {
#pragma unroll
                for (int h = 0; h < 8; h++)
                    ebuf[warp][le * 8 + h] *= inv[h];
            }
        }
        __syncwarp();

        int le = 0;
        for (; le + 2 <= deg; le += 2) {
            int s0 = d_csrsrc[beg + le];
            int s1 = d_csrsrc[beg + le + 1];
            const float4* g0 = (const float4*)(d_g + (size_t)s0 * HIDD);
            const float4* g1 = (const float4*)(d_g + (size_t)s1 * HIDD);
#pragma unroll
            for (int t = 0; t < 6; t++) {
                int j4 = lane + 32 * t;
                float a0 = ebuf[warp][le * 8 + head_t[t]];
                float a1 = ebuf[warp][(le + 1) * 8 + head_t[t]];
                float4 v0 = g0[j4], v1 = g1[j4];
                acc4[t].x += a0 * v0.x + a1 * v1.x;
                acc4[t].y += a0 * v0.y + a1 * v1.y;
                acc4[t].z += a0 * v0.z + a1 * v1.z;
                acc4[t].w += a0 * v0.w + a1 * v1.w;
            }
        }
        if (le < deg) {
            int s0 = d_csrsrc[beg + le];
            const float4* g0 = (const float4*)(d_g + (size_t)s0 * HIDD);
#pragma unroll
            for (int t = 0; t < 6; t++) {
                int j4 = lane + 32 * t;
                float a0 = ebuf[warp][le * 8 + head_t[t]];
                float4 v0 = g0[j4];
                acc4[t].x += a0 * v0.x;
                acc4[t].y += a0 * v0.y;
                acc4[t].z += a0 * v0.z;
                acc4[t].w += a0 * v0.w;
            }
        }
    } else {
        float mx[8];
#pragma unroll
        for (int h = 0; h < 8; h++) mx[h] = -1e30f;
        for (int i0 = beg; i0 < end; i0 += 32) {
            int idx = i0 + lane;
            bool v = idx < end;
            int s = v ? d_csrsrc[idx] : 0;
#pragma unroll
            for (int h = 0; h < 8; h++) {
                float e = -1e30f;
                if (v) {
                    e = d_as[s * 8 + h] + ad[h];
                    e = e > 0.f ? e : 0.2f * e;
                    d_e[(size_t)idx * 8 + h] = e;
                }
                mx[h] = fmaxf(mx[h], e);
            }
        }
#pragma unroll
        for (int h = 0; h < 8; h++)
            for (int off = 16; off; off >>= 1)
                mx[h] = fmaxf(mx[h], __shfl_xor_sync(0xffffffffu, mx[h], off));

        float sm[8];
#pragma unroll
        for (int h = 0; h < 8; h++) sm[h] = 0.f;
        for (int i0 = beg; i0 < end; i0 += 32) {
            int idx = i0 + lane;
            bool v = idx < end;
#pragma unroll
            for (int h = 0; h < 8; h++) {
                if (v) {
                    float p = __expf(d_e[(size_t)idx * 8 + h] - mx[h]);
                    d_e[(size_t)idx * 8 + h] = p;
                    sm[h] += p;
                }
            }
        }
#pragma unroll
        for (int h = 0; h < 8; h++)
            for (int off = 16; off; off >>= 1)
                sm[h] += __shfl_xor_sync(0xffffffffu, sm[h], off);
        if (lane == 0) {
#pragma unroll
            for (int h = 0; h < 8; h++) s_alpha[warp][h] = 1.f / (sm[h] + 1e-16f);
        }
        __syncwarp();
        float inv8 = s_alpha[warp][lane & 7];
        for (int idx = beg; idx < end; idx++) {
            int s = d_csrsrc[idx];
            if (lane < 8) s_alpha[warp][lane] = d_e[(size_t)idx * 8 + lane] * inv8;
            __syncwarp();
            const float4* g0 = (const float4*)(d_g + (size_t)s * HIDD);
#pragma unroll
            for (int t = 0; t < 6; t++) {
                int j4 = lane + 32 * t;
                float a0 = s_alpha[warp][head_t[t]];
                float4 v0 = g0[j4];
                acc4[t].x += a0 * v0.x;
                acc4[t].y += a0 * v0.y;
                acc4[t].z += a0 * v0.z;
                acc4[t].w += a0 * v0.w;
            }
            __syncwarp();
        }
    }

#pragma unroll
    for (int t = 0; t < 6; t++) {
        int j = 4 * (lane + 32 * t);
        float4 b4 = *(const float4*)(bias + j);
        float4 v = acc4[t];
        v.x = fmaxf(v.x + b4.x, 0.f);
        v.y = fmaxf(v.y + b4.y, 0.f);
        v.z = fmaxf(v.z + b4.z, 0.f);
        v.w = fmaxf(v.w + b4.w, 0.f);
        if (write_h) *(float4*)&d_h[(size_t)n * HIDD + j] = v;
        write_split4(n, j, v);
    }
}

// ---------------- pooling / fc ----------------
__global__ void k_pool() {
    int b = blockIdx.x;
    int j = blockIdx.y * 256 + threadIdx.x;
    int beg = d_gstart[b], end = d_gstart[b + 1];
    float s = 0.f;
    for (int n = beg; n < end; n++) s += d_h[(size_t)n * HIDD + j];
    float cnt = (float)(end - beg);
    d_pool[b * HIDD + j] = s / fmaxf(cnt, 1.0f);
}

__global__ void k_fc(const float* __restrict__ W, const float* __restrict__ b,
                     float* __restrict__ out) {
    int id = blockIdx.x * 256 + threadIdx.x;
    if (id >= NGB * EMB) return;
    int bb = id / EMB, k = id % EMB;
    float s = b[k];
    for (int j = 0; j < HIDD; j++) s += d_pool[bb * HIDD + j] * W[j * EMB + k];
    out[id] = s;
}

// ---------------- host launch ----------------
extern "C" void kernel_launch(void* const* d_in, const int* in_sizes, int n_in,
                              void* d_out, int out_size) {
    const float* x     = (const float*)d_in[0];
    const int*   ei    = (const int*)d_in[1];
    const int*   batch = (const int*)d_in[2];
    const float* projW = (const float*)d_in[3];
    const float* projb = (const float*)d_in[4];
    const float* convW = (const float*)d_in[5];
    const float* attS  = (const float*)d_in[6];
    const float* attD  = (const float*)d_in[7];
    const float* convb = (const float*)d_in[8];
    const float* fcW   = (const float*)d_in[9];
    const float* fcb   = (const float*)d_in[10];
    float* out = (float*)d_out;

    static bool attr_set = false;
    if (!attr_set) {
        cudaFuncSetAttribute(k_gemm_hmma, cudaFuncAttributeMaxDynamicSharedMemorySize, SMEM_GEMM);
        attr_set = true;
    }

    void* pW = nullptr;
    cudaGetSymbolAddress(&pW, d_WcatT);
    const __nv_bfloat16* Wcat = (const __nv_bfloat16*)pW;

    k_zero_deg<<<(NN + 255) / 256, 256>>>();
    k_hist<<<(EA + 255) / 256, 256>>>(ei);
    k_scan<<<1, 1024>>>();
    k_scatter<<<(EA + 255) / 256, 256>>>(ei);
    k_gstart<<<(NN + 255) / 256, 256>>>(batch);
    k_proj<<<(NN * HIDD + 255) / 256, 256>>>(x, projW, projb);
    k_split_w<<<(NL * HIDD * HIDD + 255) / 256, 256>>>(convW);
    k_zero_asd<<<(NN * NH + 255) / 256, 256>>>();

    for (int l = 0; l < NL; l++) {
        dim3 gg(HIDD / 256, (NN + 127) / 128);   // 3 x 157
        k_gemm_hmma<<<gg, 256, SMEM_GEMM>>>(Wcat + (size_t)l * HIDD * KCAT,
                                            attS + l * HIDD, attD + l * HIDD);
        k_attn<<<NN / 8, 256>>>(convb + l * HIDD, (l == NL - 1) ? 1 : 0);
        if (l != NL - 1) k_zero_asd<<<(NN * NH + 255) / 256, 256>>>();
    }

    dim3 gp(NGB, 3);
    k_pool<<<gp, 256>>>();
    k_fc<<<(NGB * EMB + 255) / 256, 256>>>(fcW, fcb, out);
}

// round 11
// speedup vs baseline: 1.0695x; 1.0324x over previous
#include <cuda_runtime.h>
#include <cuda_bf16.h>
#include <cstdint>

#define NN 20000
#define EE 320000
#define EA 340000      // E + N self loops
#define HIDD 768
#define NH 8
#define NC 96
#define NL 16
#define NGB 16
#define EMB 512
#define KCAT 2304      // 3 * HIDD (bf16 split: hi*hi + lo*hi + hi*lo)
#define MAXD 64        // smem softmax cache cap (recompute path beyond)

// ---------------- scratch (device globals; no allocations) ----------------
__device__ float d_h[NN * HIDD];
__device__ float d_g[NN * HIDD];
__device__ float d_as0[NN * NH];
__device__ float d_ad0[NN * NH];
__device__ float d_as1[NN * NH];
__device__ float d_ad1[NN * NH];
__device__ int   d_deg[NN];
__device__ int   d_rowptr[NN + 1];
__device__ int   d_cursor[NN];
__device__ int   d_csrsrc[EA];
__device__ int   d_gstart[NGB + 1];
__device__ float d_pool[NGB * HIDD];
__device__ __nv_bfloat16 d_Acat[(size_t)NN * KCAT];           // h split, [N, 2304]
__device__ __nv_bfloat16 d_WcatT[(size_t)NL * HIDD * KCAT];   // W^T split, [L, 768n, 2304k]

// ---------------- CSR build ----------------
__global__ void k_zero_deg() {
    int i = blockIdx.x * 256 + threadIdx.x;
    if (i < NN) d_deg[i] = 0;
}

__global__ void k_hist(const int* __restrict__ ei) {
    int i = blockIdx.x * 256 + threadIdx.x;
    if (i >= EA) return;
    int dst = (i < EE) ? ei[EE + i] : (i - EE);
    atomicAdd(&d_deg[dst], 1);
}

__global__ void k_scan() {
    __shared__ int sdata[1024];
    __shared__ int carry;
    int tid = threadIdx.x;
    if (tid == 0) { carry = 0; d_rowptr[0] = 0; }
    __syncthreads();
    for (int base = 0; base < NN; base += 1024) {
        int i = base + tid;
        int v = (i < NN) ? d_deg[i] : 0;
        sdata[tid] = v;
        __syncthreads();
        for (int off = 1; off < 1024; off <<= 1) {
            int t = (tid >= off) ? sdata[tid - off] : 0;
            __syncthreads();
            sdata[tid] += t;
            __syncthreads();
        }
        int incl = sdata[tid] + carry;
        if (i < NN) d_rowptr[i + 1] = incl;
        __syncthreads();
        if (tid == 1023) carry = incl;
        __syncthreads();
    }
    for (int i = tid; i < NN; i += 1024) d_cursor[i] = d_rowptr[i];
}

__global__ void k_scatter(const int* __restrict__ ei) {
    int i = blockIdx.x * 256 + threadIdx.x;
    if (i >= EA) return;
    int src, dst;
    if (i < EE) { src = ei[i]; dst = ei[EE + i]; }
    else        { src = i - EE; dst = src; }
    int slot = atomicAdd(&d_cursor[dst], 1);
    d_csrsrc[slot] = src;
}

__global__ void k_gstart(const int* __restrict__ batch) {
    int n = blockIdx.x * 256 + threadIdx.x;
    if (n >= NN) return;
    int b = batch[n];
    if (n == 0) {
        for (int bb = 0; bb <= b; bb++) d_gstart[bb] = 0;
    } else {
        int pb = batch[n - 1];
        if (pb != b) for (int bb = pb + 1; bb <= b; bb++) d_gstart[bb] = n;
    }
    if (n == NN - 1) {
        for (int bb = b + 1; bb <= NGB; bb++) d_gstart[bb] = NN;
    }
}

__global__ void k_zero_asd0() {
    int i = blockIdx.x * 256 + threadIdx.x;
    if (i < NN * NH) { d_as0[i] = 0.f; d_ad0[i] = 0.f; }
}

// ---------------- split write helpers ----------------
__device__ __forceinline__ void write_split(int n, int k, float v) {
    __nv_bfloat16 hi = __float2bfloat16(v);
    __nv_bfloat16 lo = __float2bfloat16(v - __bfloat162float(hi));
    size_t base = (size_t)n * KCAT;
    d_Acat[base + k]            = hi;
    d_Acat[base + HIDD + k]     = lo;
    d_Acat[base + 2 * HIDD + k] = hi;
}

__device__ __forceinline__ void write_split4(int n, int j, float4 v) {
    float vv[4] = {v.x, v.y, v.z, v.w};
    __nv_bfloat162 hp[2], lp[2];
#pragma unroll
    for (int q = 0; q < 2; q++) {
        __nv_bfloat16 h0 = __float2bfloat16(vv[2 * q]);
        __nv_bfloat16 h1 = __float2bfloat16(vv[2 * q + 1]);
        __nv_bfloat16 l0 = __float2bfloat16(vv[2 * q]     - __bfloat162float(h0));
        __nv_bfloat16 l1 = __float2bfloat16(vv[2 * q + 1] - __bfloat162float(h1));
        hp[q] = __nv_bfloat162(h0, h1);
        lp[q] = __nv_bfloat162(l0, l1);
    }
    size_t base = (size_t)n * KCAT;
    __nv_bfloat162* p0 = (__nv_bfloat162*)&d_Acat[base + j];
    __nv_bfloat162* p1 = (__nv_bfloat162*)&d_Acat[base + HIDD + j];
    __nv_bfloat162* p2 = (__nv_bfloat162*)&d_Acat[base + 2 * HIDD + j];
    p0[0] = hp[0]; p0[1] = hp[1];
    p1[0] = lp[0]; p1[1] = lp[1];
    p2[0] = hp[0]; p2[1] = hp[1];
}

// ---------------- input projection (split only) ----------------
__global__ void k_proj(const float* __restrict__ x, const float* __restrict__ W,
                       const float* __restrict__ b) {
    int id = blockIdx.x * 256 + threadIdx.x;
    if (id >= NN * HIDD) return;
    int n = id / HIDD, j = id % HIDD;
    float s = b[j];
#pragma unroll
    for (int f = 0; f < 5; f++) s += x[n * 5 + f] * W[f * HIDD + j];
    write_split(n, j, s);
}

// ---------------- bf16 split: weights (once) ----------------
__global__ void k_split_w(const float* __restrict__ convW) {
    int id = blockIdx.x * 256 + threadIdx.x;
    if (id >= NL * HIDD * HIDD) return;
    int l = id / (HIDD * HIDD);
    int rem = id % (HIDD * HIDD);
    int k = rem / HIDD, n = rem % HIDD;
    float v = convW[id];
    __nv_bfloat16 hi = __float2bfloat16(v);
    __nv_bfloat16 lo = __float2bfloat16(v - __bfloat162float(hi));
    size_t base = ((size_t)l * HIDD + n) * KCAT;
    d_WcatT[base + k]            = hi;
    d_WcatT[base + HIDD + k]     = hi;
    d_WcatT[base + 2 * HIDD + k] = lo;
}

// =====================================================================
// HMMA GEMM: 128x256 CTA tile, 64x64 warp tile, BK=64, 4-stage cp.async
// Fused epilogue: d_g store + att dot products into asb/adb (atomicAdd)
// =====================================================================
#define BK 64
#define STAGES 4
#define STG_A 16384
#define STG_B 32768
#define SMEM_GEMM (STAGES * (STG_A + STG_B))   // 196608

__device__ __forceinline__ uint32_t swz(uint32_t b) { return b ^ ((b >> 3) & 0x70); }

__device__ __forceinline__ uint32_t smem_u32(const void* p) {
    uint32_t a;
    asm("{ .reg .u64 t; cvta.to.shared.u64 t, %1; cvt.u32.u64 %0, t; }" : "=r"(a) : "l"(p));
    return a;
}

#define CP_ASYNC(dst, src, sz) \
    asm volatile("cp.async.cg.shared.global [%0], [%1], 16, %2;" \
        :: "r"(dst), "l"(src), "r"(sz))
#define CP_COMMIT() asm volatile("cp.async.commit_group;")
#define CP_WAIT2()  asm volatile("cp.async.wait_group 2;")

#define LDMX4(r0, r1, r2, r3, a) \
    asm volatile("ldmatrix.sync.aligned.m8n8.x4.shared.b16 {%0,%1,%2,%3}, [%4];" \
        : "=r"(r0), "=r"(r1), "=r"(r2), "=r"(r3) : "r"(a))

#define MMA16816(d, a, b) \
    asm volatile("mma.sync.aligned.m16n8k16.row.col.f32.bf16.bf16.f32 " \
        "{%0,%1,%2,%3}, {%4,%5,%6,%7}, {%8,%9}, {%0,%1,%2,%3};" \
        : "+f"((d)[0]), "+f"((d)[1]), "+f"((d)[2]), "+f"((d)[3]) \
        : "r"((a)[0]), "r"((a)[1]), "r"((a)[2]), "r"((a)[3]), "r"((b)[0]), "r"((b)[1]))

__global__ __launch_bounds__(256, 1) void k_gemm_hmma(
    const __nv_bfloat16* __restrict__ Wl,
    const float* __restrict__ attS, const float* __restrict__ attD,
    float* __restrict__ asb, float* __restrict__ adb)
{
    extern __shared__ __align__(128) char smem[];
    uint32_t sA = smem_u32(smem);
    uint32_t sB = sA + STAGES * STG_A;

    const int tid = threadIdx.x;
    const int lane = tid & 31, warp = tid >> 5;
    const int wm = warp & 1, wn = warp >> 1;         // 2 m-warps x 4 n-warps
    const int mtile = blockIdx.y, ntile = blockIdx.x;
    const int mbase = mtile * 128;
    const int nbase = ntile * 256;

    const __nv_bfloat16* Ag = d_Acat;

    auto issue_stage = [&](int kt, int st) {
        int k0 = kt * BK;
        uint32_t a_dst = sA + st * STG_A;
#pragma unroll
        for (int it = 0; it < 4; it++) {
            int id = it * 256 + tid;
            int row = id >> 3, ck = id & 7;
            int gr = mbase + row;
            const __nv_bfloat16* srcA = Ag + (size_t)gr * KCAT + k0 + ck * 8;
            CP_ASYNC(a_dst + swz(row * 128 + ck * 16), srcA, (gr < NN) ? 16 : 0);
        }
        uint32_t b_dst = sB + st * STG_B;
#pragma unroll
        for (int it = 0; it < 8; it++) {
            int id = it * 256 + tid;
            int row = id >> 3, ck = id & 7;
            const __nv_bfloat16* srcB = Wl + (size_t)(nbase + row) * KCAT + k0 + ck * 8;
            CP_ASYNC(b_dst + swz(row * 128 + ck * 16), srcB, 16);
        }
        CP_COMMIT();
    };

    issue_stage(0, 0);
    issue_stage(1, 1);
    issue_stage(2, 2);

    float acc[4][8][4];
#pragma unroll
    for (int i = 0; i < 4; i++)
#pragma unroll
        for (int j = 0; j < 8; j++)
#pragma unroll
            for (int c = 0; c < 4; c++) acc[i][j][c] = 0.f;

    const int NKT = KCAT / BK;
    for (int kt = 0; kt < NKT; kt++) {
        CP_WAIT2();
        __syncthreads();
        if (kt + 3 < NKT) issue_stage(kt + 3, (kt + 3) % STAGES);
        else CP_COMMIT();

        int st = kt % STAGES;
        uint32_t aS = sA + st * STG_A;
        uint32_t bS = sB + st * STG_B;

#pragma unroll
        for (int ks = 0; ks < 4; ks++) {
            uint32_t afr[4][4];
#pragma unroll
            for (int im = 0; im < 4; im++) {
                int row = wm * 64 + im * 16 + (lane & 15);
                int kk = ks * 16 + (lane >> 4) * 8;
                LDMX4(afr[im][0], afr[im][1], afr[im][2], afr[im][3],
                      aS + swz(row * 128 + kk * 2));
            }
            uint32_t bfr[8][2];
#pragma unroll
            for (int pr = 0; pr < 4; pr++) {
                int nrow = wn * 64 + pr * 16 + (lane & 7) + ((lane & 16) ? 8 : 0);
                int kk = ks * 16 + ((lane & 8) ? 8 : 0);
                uint32_t r0, r1, r2, r3;
                LDMX4(r0, r1, r2, r3, bS + swz(nrow * 128 + kk * 2));
                bfr[pr * 2][0] = r0;     bfr[pr * 2][1] = r1;
                bfr[pr * 2 + 1][0] = r2; bfr[pr * 2 + 1][1] = r3;
            }
#pragma unroll
            for (int im = 0; im < 4; im++)
#pragma unroll
                for (int jn = 0; jn < 8; jn++)
                    MMA16816(acc[im][jn], afr[im], bfr[jn]);
        }
        __syncthreads();
    }

    // ---------------- fused epilogue ----------------
    const int base0 = nbase + wn * 64;
    const int hA = base0 / 96;
    float ps[4][2][2];
    float pd[4][2][2];
#pragma unroll
    for (int a = 0; a < 4; a++)
#pragma unroll
        for (int b = 0; b < 2; b++)
#pragma unroll
            for (int c = 0; c < 2; c++) { ps[a][b][c] = 0.f; pd[a][b][c] = 0.f; }

#pragma unroll
    for (int jn = 0; jn < 8; jn++) {
        int col = base0 + jn * 8 + (lane & 3) * 2;
        int slot = (col / 96) - hA;
        float as0 = __ldg(attS + col), as1 = __ldg(attS + col + 1);
        float ad0 = __ldg(attD + col), ad1 = __ldg(attD + col + 1);
#pragma unroll
        for (int im = 0; im < 4; im++) {
            int r0 = mbase + wm * 64 + im * 16 + (lane >> 2);
            if (r0 < NN)
                *(float2*)&d_g[(size_t)r0 * HIDD + col] =
                    make_float2(acc[im][jn][0], acc[im][jn][1]);
            if (r0 + 8 < NN)
                *(float2*)&d_g[(size_t)(r0 + 8) * HIDD + col] =
                    make_float2(acc[im][jn][2], acc[im][jn][3]);
            ps[im][0][slot] += acc[im][jn][0] * as0 + acc[im][jn][1] * as1;
            pd[im][0][slot] += acc[im][jn][0] * ad0 + acc[im][jn][1] * ad1;
            ps[im][1][slot] += acc[im][jn][2] * as0 + acc[im][jn][3] * as1;
            pd[im][1][slot] += acc[im][jn][2] * ad0 + acc[im][jn][3] * ad1;
        }
    }
#pragma unroll
    for (int im = 0; im < 4; im++)
#pragma unroll
        for (int rh = 0; rh < 2; rh++)
#pragma unroll
            for (int sl = 0; sl < 2; sl++) {
                float vs = ps[im][rh][sl], vd = pd[im][rh][sl];
                vs += __shfl_xor_sync(0xffffffffu, vs, 1);
                vs += __shfl_xor_sync(0xffffffffu, vs, 2);
                vd += __shfl_xor_sync(0xffffffffu, vd, 1);
                vd += __shfl_xor_sync(0xffffffffu, vd, 2);
                if ((lane & 3) == 0) {
                    int row = mbase + wm * 64 + im * 16 + (lane >> 2) + rh * 8;
                    int h = hA + sl;
                    if (row < NN && h < NH) {
                        atomicAdd(&asb[row * 8 + h], vs);
                        atomicAdd(&adb[row * 8 + h], vd);
                    }
                }
            }
}

// =====================================================================
// Attention: per-warp softmax (R8) + pair-balanced channel-split gather.
// block = 256 = 8 nodes. Zeros the NEXT layer's as/ad buffers.
// =====================================================================
__global__ __launch_bounds__(256) void k_attn(
    const float* __restrict__ cas, const float* __restrict__ cad,
    float* __restrict__ nas, float* __restrict__ nad,
    const float* __restrict__ bias, int write_h)
{
    __shared__ float ebuf[8][MAXD * 8];   // 16 KB alpha cache
    __shared__ float smx[8][8];
    __shared__ float sinv[8][8];

    const int warp = threadIdx.x >> 5, lane = threadIdx.x & 31;
    const int blkbase = blockIdx.x * 8;
    const int n = blkbase + warp;

    // zero next layer's attention coefficient slots for owned node
    if (lane < 8) { nas[n * 8 + lane] = 0.f; nad[n * 8 + lane] = 0.f; }

    const int beg = d_rowptr[n], end = d_rowptr[n + 1];
    const int deg = end - beg;

    const float4* adp = (const float4*)(cad + n * 8);
    float4 ad0 = adp[0], ad1 = adp[1];
    float ad[8] = {ad0.x, ad0.y, ad0.z, ad0.w, ad1.x, ad1.y, ad1.z, ad1.w};

    // ---------- phase 1: per-warp softmax for own node ----------
    float mx[8];
#pragma unroll
    for (int h = 0; h < 8; h++) mx[h] = -1e30f;
    if (deg <= MAXD) {
#pragma unroll
        for (int it = 0; it < 2; it++) {
            int le = it * 32 + lane;
            if (le < deg) {
                int s = d_csrsrc[beg + le];
                const float4* ap = (const float4*)(cas + s * 8);
                float4 a0 = ap[0], a1 = ap[1];
                float ev[8] = {a0.x, a0.y, a0.z, a0.w, a1.x, a1.y, a1.z, a1.w};
#pragma unroll
                for (int h = 0; h < 8; h++) {
                    float e = ev[h] + ad[h];
                    e = e > 0.f ? e : 0.2f * e;
                    ebuf[warp][le * 8 + h] = e;
                    mx[h] = fmaxf(mx[h], e);
                }
            }
        }
    } else {
        for (int i0 = beg + lane; i0 < end; i0 += 32) {
            int s = d_csrsrc[i0];
            const float4* ap = (const float4*)(cas + s * 8);
            float4 a0 = ap[0], a1 = ap[1];
            float ev[8] = {a0.x, a0.y, a0.z, a0.w, a1.x, a1.y, a1.z, a1.w};
#pragma unroll
            for (int h = 0; h < 8; h++) {
                float e = ev[h] + ad[h];
                e = e > 0.f ? e : 0.2f * e;
                mx[h] = fmaxf(mx[h], e);
            }
        }
    }
#pragma unroll
    for (int h = 0; h < 8; h++)
        for (int off = 16; off; off >>= 1)
            mx[h] = fmaxf(mx[h], __shfl_xor_sync(0xffffffffu, mx[h], off));
    __syncwarp();

    float sm[8];
#pragma unroll
    for (int h = 0; h < 8; h++) sm[h] = 0.f;
    if (deg <= MAXD) {
#pragma unroll
        for (int it = 0; it < 2; it++) {
            int le = it * 32 + lane;
            if (le < deg) {
#pragma unroll
                for (int h = 0; h < 8; h++) {
                    float p = __expf(ebuf[warp][le * 8 + h] - mx[h]);
                    ebuf[warp][le * 8 + h] = p;
                    sm[h] += p;
                }
            }
        }
    } else {
        for (int i0 = beg + lane; i0 < end; i0 += 32) {
            int s = d_csrsrc[i0];
            const float4* ap = (const float4*)(cas + s * 8);
            float4 a0 = ap[0], a1 = ap[1];
            float ev[8] = {a0.x, a0.y, a0.z, a0.w, a1.x, a1.y, a1.z, a1.w};
#pragma unroll
            for (int h = 0; h < 8; h++) {
                float e = ev[h] + ad[h];
                e = e > 0.f ? e : 0.2f * e;
                sm[h] += __expf(e - mx[h]);
            }
        }
    }
#pragma unroll
    for (int h = 0; h < 8; h++)
        for (int off = 16; off; off >>= 1)
            sm[h] += __shfl_xor_sync(0xffffffffu, sm[h], off);
    float inv[8];
#pragma unroll
    for (int h = 0; h < 8; h++) inv[h] = 1.f / (sm[h] + 1e-16f);
    if (lane < 8) { smx[warp][lane] = mx[lane]; sinv[warp][lane] = inv[lane]; }
    __syncwarp();

    if (deg <= MAXD) {
#pragma unroll
        for (int it = 0; it < 2; it++) {
            int le = it * 32 + lane;
            if (le < deg) {
#pragma unroll
                for (int h = 0; h < 8; h++)
                    ebuf[warp][le * 8 + h] *= inv[h];
            }
        }
    }
    __syncthreads();

    // ---------- phase 2: pair-balanced gather ----------
    const int pw = warp & 1;
    const int q0 = warp & ~1;            // block-local node pair
    int slot_t[3], head_t[3], j4_t[3];
#pragma unroll
    for (int t = 0; t < 3; t++) {
        slot_t[t] = pw * 3 + t;
        j4_t[t] = lane + 32 * slot_t[t];
        head_t[t] = j4_t[t] / 24;
    }

#pragma unroll
    for (int qi = 0; qi < 2; qi++) {
        int q = q0 + qi;
        int nq = blkbase + q;
        int bq = d_rowptr[nq], eq = d_rowptr[nq + 1];
        int dq = eq - bq;

        float4 acc4[3];
#pragma unroll
        for (int t = 0; t < 3; t++) acc4[t] = make_float4(0.f, 0.f, 0.f, 0.f);

        if (dq <= MAXD) {
            int le = 0;
            for (; le + 4 <= dq; le += 4) {
                int s0 = d_csrsrc[bq + le];
                int s1 = d_csrsrc[bq + le + 1];
                int s2 = d_csrsrc[bq + le + 2];
                int s3 = d_csrsrc[bq + le + 3];
                const float4* g0 = (const float4*)(d_g + (size_t)s0 * HIDD);
                const float4* g1 = (const float4*)(d_g + (size_t)s1 * HIDD);
                const float4* g2 = (const float4*)(d_g + (size_t)s2 * HIDD);
                const float4* g3 = (const float4*)(d_g + (size_t)s3 * HIDD);
#pragma unroll
                for (int t = 0; t < 3; t++) {
                    int j4 = j4_t[t], hh = head_t[t];
                    float a0 = ebuf[q][le * 8 + hh];
                    float a1 = ebuf[q][(le + 1) * 8 + hh];
                    float a2 = ebuf[q][(le + 2) * 8 + hh];
                    float a3 = ebuf[q][(le + 3) * 8 + hh];
                    float4 v0 = g0[j4], v1 = g1[j4], v2 = g2[j4], v3 = g3[j4];
                    acc4[t].x += a0 * v0.x + a1 * v1.x + a2 * v2.x + a3 * v3.x;
                    acc4[t].y += a0 * v0.y + a1 * v1.y + a2 * v2.y + a3 * v3.y;
                    acc4[t].z += a0 * v0.z + a1 * v1.z + a2 * v2.z + a3 * v3.z;
                    acc4[t].w += a0 * v0.w + a1 * v1.w + a2 * v2.w + a3 * v3.w;
                }
            }
            for (; le < dq; le++) {
                int s0 = d_csrsrc[bq + le];
                const float4* g0 = (const float4*)(d_g + (size_t)s0 * HIDD);
#pragma unroll
                for (int t = 0; t < 3; t++) {
                    float a0 = ebuf[q][le * 8 + head_t[t]];
                    float4 v0 = g0[j4_t[t]];
                    acc4[t].x += a0 * v0.x;
                    acc4[t].y += a0 * v0.y;
                    acc4[t].z += a0 * v0.z;
                    acc4[t].w += a0 * v0.w;
                }
            }
        } else {
            float adq[3], mxq[3], invq[3];
#pragma unroll
            for (int t = 0; t < 3; t++) {
                adq[t] = __ldg(cad + nq * 8 + head_t[t]);
                mxq[t] = smx[q][head_t[t]];
                invq[t] = sinv[q][head_t[t]];
            }
            for (int le = 0; le < dq; le++) {
                int s0 = d_csrsrc[bq + le];
                const float4* g0 = (const float4*)(d_g + (size_t)s0 * HIDD);
#pragma unroll
                for (int t = 0; t < 3; t++) {
                    float e = __ldg(cas + s0 * 8 + head_t[t]) + adq[t];
                    e = e > 0.f ? e : 0.2f * e;
                    float a0 = __expf(e - mxq[t]) * invq[t];
                    float4 v0 = g0[j4_t[t]];
                    acc4[t].x += a0 * v0.x;
                    acc4[t].y += a0 * v0.y;
                    acc4[t].z += a0 * v0.z;
                    acc4[t].w += a0 * v0.w;
                }
            }
        }

        // epilogue for this node's 3 slots
#pragma unroll
        for (int t = 0; t < 3; t++) {
            int j = 4 * j4_t[t];
            float4 b4 = *(const float4*)(bias + j);
            float4 v = acc4[t];
            v.x = fmaxf(v.x + b4.x, 0.f);
            v.y = fmaxf(v.y + b4.y, 0.f);
            v.z = fmaxf(v.z + b4.z, 0.f);
            v.w = fmaxf(v.w + b4.w, 0.f);
            if (write_h) *(float4*)&d_h[(size_t)nq * HIDD + j] = v;
            write_split4(nq, j, v);
        }
    }
}

// ---------------- pooling / fc ----------------
__global__ void k_pool() {
    int b = blockIdx.x;
    int j = blockIdx.y * 256 + threadIdx.x;
    int beg = d_gstart[b], end = d_gstart[b + 1];
    float s = 0.f;
    for (int n = beg; n < end; n++) s += d_h[(size_t)n * HIDD + j];
    float cnt = (float)(end - beg);
    d_pool[b * HIDD + j] = s / fmaxf(cnt, 1.0f);
}

__global__ void k_fc(const float* __restrict__ W, const float* __restrict__ b,
                     float* __restrict__ out) {
    int id = blockIdx.x * 256 + threadIdx.x;
    if (id >= NGB * EMB) return;
    int bb = id / EMB, k = id % EMB;
    float s = b[k];
    for (int j = 0; j < HIDD; j++) s += d_pool[bb * HIDD + j] * W[j * EMB + k];
    out[id] = s;
}

// ---------------- host launch ----------------
extern "C" void kernel_launch(void* const* d_in, const int* in_sizes, int n_in,
                              void* d_out, int out_size) {
    const float* x     = (const float*)d_in[0];
    const int*   ei    = (const int*)d_in[1];
    const int*   batch = (const int*)d_in[2];
    const float* projW = (const float*)d_in[3];
    const float* projb = (const float*)d_in[4];
    const float* convW = (const float*)d_in[5];
    const float* attS  = (const float*)d_in[6];
    const float* attD  = (const float*)d_in[7];
    const float* convb = (const float*)d_in[8];
    const float* fcW   = (const float*)d_in[9];
    const float* fcb   = (const float*)d_in[10];
    float* out = (float*)d_out;

    static bool attr_set = false;
    if (!attr_set) {
        cudaFuncSetAttribute(k_gemm_hmma, cudaFuncAttributeMaxDynamicSharedMemorySize, SMEM_GEMM);
        attr_set = true;
    }

    void* pW = nullptr;
    cudaGetSymbolAddress(&pW, d_WcatT);
    const __nv_bfloat16* Wcat = (const __nv_bfloat16*)pW;
    void *pa0, *pd0, *pa1, *pd1;
    cudaGetSymbolAddress(&pa0, d_as0);
    cudaGetSymbolAddress(&pd0, d_ad0);
    cudaGetSymbolAddress(&pa1, d_as1);
    cudaGetSymbolAddress(&pd1, d_ad1);
    float* asb[2] = {(float*)pa0, (float*)pa1};
    float* adb[2] = {(float*)pd0, (float*)pd1};

    k_zero_deg<<<(NN + 255) / 256, 256>>>();
    k_hist<<<(EA + 255) / 256, 256>>>(ei);
    k_scan<<<1, 1024>>>();
    k_scatter<<<(EA + 255) / 256, 256>>>(ei);
    k_gstart<<<(NN + 255) / 256, 256>>>(batch);
    k_proj<<<(NN * HIDD + 255) / 256, 256>>>(x, projW, projb);
    k_split_w<<<(NL * HIDD * HIDD + 255) / 256, 256>>>(convW);
    k_zero_asd0<<<(NN * NH + 255) / 256, 256>>>();

    for (int l = 0; l < NL; l++) {
        int cur = l & 1, nxt = cur ^ 1;
        dim3 gg(HIDD / 256, (NN + 127) / 128);   // 3 x 157
        k_gemm_hmma<<<gg, 256, SMEM_GEMM>>>(Wcat + (size_t)l * HIDD * KCAT,
                                            attS + l * HIDD, attD + l * HIDD,
                                            asb[cur], adb[cur]);
        k_attn<<<NN / 8, 256>>>(asb[cur], adb[cur], asb[nxt], adb[nxt],
                                convb + l * HIDD, (l == NL - 1) ? 1 : 0);
    }

    dim3 gp(NGB, 3);
    k_pool<<<gp, 256>>>();
    k_fc<<<(NGB * EMB + 255) / 256, 256>>>(fcW, fcb, out);
}

// round 12
// speedup vs baseline: 1.0810x; 1.0107x over previous
#include <cuda_runtime.h>
#include <cuda_bf16.h>
#include <cstdint>

#define NN 20000
#define EE 320000
#define EA 340000      // E + N self loops
#define HIDD 768
#define NH 8
#define NC 96
#define NL 16
#define NGB 16
#define EMB 512
#define KCAT 2304      // 3 * HIDD (bf16 split: hi*hi + lo*hi + hi*lo)
#define MAXD 64        // smem softmax cache cap (recompute path beyond)

// ---------------- scratch (device globals; no allocations) ----------------
__device__ float d_h[NN * HIDD];
__device__ float d_g[NN * HIDD];
__device__ float d_as0[NN * NH];
__device__ float d_ad0[NN * NH];
__device__ float d_as1[NN * NH];
__device__ float d_ad1[NN * NH];
__device__ int   d_deg[NN];
__device__ int   d_rowptr[NN + 1];
__device__ int   d_cursor[NN];
__device__ int   d_csrsrc[EA];
__device__ int   d_gstart[NGB + 1];
__device__ float d_pool[NGB * HIDD];
__device__ __nv_bfloat16 d_Acat[(size_t)NN * KCAT];           // h split, [N, 2304]
__device__ __nv_bfloat16 d_WcatT[(size_t)NL * HIDD * KCAT];   // W^T split, [L, 768n, 2304k]

// ---------------- CSR build ----------------
__global__ void k_zero_deg() {
    int i = blockIdx.x * 256 + threadIdx.x;
    if (i < NN) d_deg[i] = 0;
}

__global__ void k_hist(const int* __restrict__ ei) {
    int i = blockIdx.x * 256 + threadIdx.x;
    if (i >= EA) return;
    int dst = (i < EE) ? ei[EE + i] : (i - EE);
    atomicAdd(&d_deg[dst], 1);
}

__global__ void k_scan() {
    __shared__ int sdata[1024];
    __shared__ int carry;
    int tid = threadIdx.x;
    if (tid == 0) { carry = 0; d_rowptr[0] = 0; }
    __syncthreads();
    for (int base = 0; base < NN; base += 1024) {
        int i = base + tid;
        int v = (i < NN) ? d_deg[i] : 0;
        sdata[tid] = v;
        __syncthreads();
        for (int off = 1; off < 1024; off <<= 1) {
            int t = (tid >= off) ? sdata[tid - off] : 0;
            __syncthreads();
            sdata[tid] += t;
            __syncthreads();
        }
        int incl = sdata[tid] + carry;
        if (i < NN) d_rowptr[i + 1] = incl;
        __syncthreads();
        if (tid == 1023) carry = incl;
        __syncthreads();
    }
    for (int i = tid; i < NN; i += 1024) d_cursor[i] = d_rowptr[i];
}

__global__ void k_scatter(const int* __restrict__ ei) {
    int i = blockIdx.x * 256 + threadIdx.x;
    if (i >= EA) return;
    int src, dst;
    if (i < EE) { src = ei[i]; dst = ei[EE + i]; }
    else        { src = i - EE; dst = src; }
    int slot = atomicAdd(&d_cursor[dst], 1);
    d_csrsrc[slot] = src;
}

__global__ void k_gstart(const int* __restrict__ batch) {
    int n = blockIdx.x * 256 + threadIdx.x;
    if (n >= NN) return;
    int b = batch[n];
    if (n == 0) {
        for (int bb = 0; bb <= b; bb++) d_gstart[bb] = 0;
    } else {
        int pb = batch[n - 1];
        if (pb != b) for (int bb = pb + 1; bb <= b; bb++) d_gstart[bb] = n;
    }
    if (n == NN - 1) {
        for (int bb = b + 1; bb <= NGB; bb++) d_gstart[bb] = NN;
    }
}

__global__ void k_zero_asd0() {
    int i = blockIdx.x * 256 + threadIdx.x;
    if (i < NN * NH) { d_as0[i] = 0.f; d_ad0[i] = 0.f; }
}

// ---------------- split write helpers ----------------
__device__ __forceinline__ void write_split(int n, int k, float v) {
    __nv_bfloat16 hi = __float2bfloat16(v);
    __nv_bfloat16 lo = __float2bfloat16(v - __bfloat162float(hi));
    size_t base = (size_t)n * KCAT;
    d_Acat[base + k]            = hi;
    d_Acat[base + HIDD + k]     = lo;
    d_Acat[base + 2 * HIDD + k] = hi;
}

__device__ __forceinline__ void write_split4(int n, int j, float4 v) {
    float vv[4] = {v.x, v.y, v.z, v.w};
    __nv_bfloat162 hp[2], lp[2];
#pragma unroll
    for (int q = 0; q < 2; q++) {
        __nv_bfloat16 h0 = __float2bfloat16(vv[2 * q]);
        __nv_bfloat16 h1 = __float2bfloat16(vv[2 * q + 1]);
        __nv_bfloat16 l0 = __float2bfloat16(vv[2 * q]     - __bfloat162float(h0));
        __nv_bfloat16 l1 = __float2bfloat16(vv[2 * q + 1] - __bfloat162float(h1));
        hp[q] = __nv_bfloat162(h0, h1);
        lp[q] = __nv_bfloat162(l0, l1);
    }
    size_t base = (size_t)n * KCAT;
    __nv_bfloat162* p0 = (__nv_bfloat162*)&d_Acat[base + j];
    __nv_bfloat162* p1 = (__nv_bfloat162*)&d_Acat[base + HIDD + j];
    __nv_bfloat162* p2 = (__nv_bfloat162*)&d_Acat[base + 2 * HIDD + j];
    p0[0] = hp[0]; p0[1] = hp[1];
    p1[0] = lp[0]; p1[1] = lp[1];
    p2[0] = hp[0]; p2[1] = hp[1];
}

// ---------------- input projection (split only) ----------------
__global__ void k_proj(const float* __restrict__ x, const float* __restrict__ W,
                       const float* __restrict__ b) {
    int id = blockIdx.x * 256 + threadIdx.x;
    if (id >= NN * HIDD) return;
    int n = id / HIDD, j = id % HIDD;
    float s = b[j];
#pragma unroll
    for (int f = 0; f < 5; f++) s += x[n * 5 + f] * W[f * HIDD + j];
    write_split(n, j, s);
}

// ---------------- bf16 split: weights (once) ----------------
__global__ void k_split_w(const float* __restrict__ convW) {
    int id = blockIdx.x * 256 + threadIdx.x;
    if (id >= NL * HIDD * HIDD) return;
    int l = id / (HIDD * HIDD);
    int rem = id % (HIDD * HIDD);
    int k = rem / HIDD, n = rem % HIDD;
    float v = convW[id];
    __nv_bfloat16 hi = __float2bfloat16(v);
    __nv_bfloat16 lo = __float2bfloat16(v - __bfloat162float(hi));
    size_t base = ((size_t)l * HIDD + n) * KCAT;
    d_WcatT[base + k]            = hi;
    d_WcatT[base + HIDD + k]     = hi;
    d_WcatT[base + 2 * HIDD + k] = lo;
}

// =====================================================================
// HMMA GEMM: 128x256 CTA tile, 64x64 warp tile, BK=64, 4-stage cp.async
// One barrier per kt (bottom barrier proven redundant: stage written at
// iter kt+1 is only read by warps that already passed the top barrier).
// =====================================================================
#define BK 64
#define STAGES 4
#define STG_A 16384
#define STG_B 32768
#define SMEM_GEMM (STAGES * (STG_A + STG_B))   // 196608

__device__ __forceinline__ uint32_t swz(uint32_t b) { return b ^ ((b >> 3) & 0x70); }

__device__ __forceinline__ uint32_t smem_u32(const void* p) {
    uint32_t a;
    asm("{ .reg .u64 t; cvta.to.shared.u64 t, %1; cvt.u32.u64 %0, t; }" : "=r"(a) : "l"(p));
    return a;
}

#define CP_ASYNC(dst, src, sz) \
    asm volatile("cp.async.cg.shared.global [%0], [%1], 16, %2;" \
        :: "r"(dst), "l"(src), "r"(sz))
#define CP_COMMIT() asm volatile("cp.async.commit_group;")
#define CP_WAIT2()  asm volatile("cp.async.wait_group 2;")

#define LDMX4(r0, r1, r2, r3, a) \
    asm volatile("ldmatrix.sync.aligned.m8n8.x4.shared.b16 {%0,%1,%2,%3}, [%4];" \
        : "=r"(r0), "=r"(r1), "=r"(r2), "=r"(r3) : "r"(a))

#define MMA16816(d, a, b) \
    asm volatile("mma.sync.aligned.m16n8k16.row.col.f32.bf16.bf16.f32 " \
        "{%0,%1,%2,%3}, {%4,%5,%6,%7}, {%8,%9}, {%0,%1,%2,%3};" \
        : "+f"((d)[0]), "+f"((d)[1]), "+f"((d)[2]), "+f"((d)[3]) \
        : "r"((a)[0]), "r"((a)[1]), "r"((a)[2]), "r"((a)[3]), "r"((b)[0]), "r"((b)[1]))

__global__ __launch_bounds__(256, 1) void k_gemm_hmma(
    const __nv_bfloat16* __restrict__ Wl,
    const float* __restrict__ attS, const float* __restrict__ attD,
    float* __restrict__ asb, float* __restrict__ adb)
{
    extern __shared__ __align__(128) char smem[];
    uint32_t sA = smem_u32(smem);
    uint32_t sB = sA + STAGES * STG_A;

    const int tid = threadIdx.x;
    const int lane = tid & 31, warp = tid >> 5;
    const int wm = warp & 1, wn = warp >> 1;         // 2 m-warps x 4 n-warps
    const int mtile = blockIdx.y, ntile = blockIdx.x;
    const int mbase = mtile * 128;
    const int nbase = ntile * 256;

    const __nv_bfloat16* Ag = d_Acat;

    auto issue_stage = [&](int kt, int st) {
        int k0 = kt * BK;
        uint32_t a_dst = sA + st * STG_A;
#pragma unroll
        for (int it = 0; it < 4; it++) {
            int id = it * 256 + tid;
            int row = id >> 3, ck = id & 7;
            int gr = mbase + row;
            const __nv_bfloat16* srcA = Ag + (size_t)gr * KCAT + k0 + ck * 8;
            CP_ASYNC(a_dst + swz(row * 128 + ck * 16), srcA, (gr < NN) ? 16 : 0);
        }
        uint32_t b_dst = sB + st * STG_B;
#pragma unroll
        for (int it = 0; it < 8; it++) {
            int id = it * 256 + tid;
            int row = id >> 3, ck = id & 7;
            const __nv_bfloat16* srcB = Wl + (size_t)(nbase + row) * KCAT + k0 + ck * 8;
            CP_ASYNC(b_dst + swz(row * 128 + ck * 16), srcB, 16);
        }
        CP_COMMIT();
    };

    issue_stage(0, 0);
    issue_stage(1, 1);
    issue_stage(2, 2);

    float acc[4][8][4];
#pragma unroll
    for (int i = 0; i < 4; i++)
#pragma unroll
        for (int j = 0; j < 8; j++)
#pragma unroll
            for (int c = 0; c < 4; c++) acc[i][j][c] = 0.f;

    const int NKT = KCAT / BK;
    for (int kt = 0; kt < NKT; kt++) {
        CP_WAIT2();
        __syncthreads();
        if (kt + 3 < NKT) issue_stage(kt + 3, (kt + 3) % STAGES);
        else CP_COMMIT();

        int st = kt % STAGES;
        uint32_t aS = sA + st * STG_A;
        uint32_t bS = sB + st * STG_B;

#pragma unroll
        for (int ks = 0; ks < 4; ks++) {
            uint32_t afr[4][4];
#pragma unroll
            for (int im = 0; im < 4; im++) {
                int row = wm * 64 + im * 16 + (lane & 15);
                int kk = ks * 16 + (lane >> 4) * 8;
                LDMX4(afr[im][0], afr[im][1], afr[im][2], afr[im][3],
                      aS + swz(row * 128 + kk * 2));
            }
            uint32_t bfr[8][2];
#pragma unroll
            for (int pr = 0; pr < 4; pr++) {
                int nrow = wn * 64 + pr * 16 + (lane & 7) + ((lane & 16) ? 8 : 0);
                int kk = ks * 16 + ((lane & 8) ? 8 : 0);
                uint32_t r0, r1, r2, r3;
                LDMX4(r0, r1, r2, r3, bS + swz(nrow * 128 + kk * 2));
                bfr[pr * 2][0] = r0;     bfr[pr * 2][1] = r1;
                bfr[pr * 2 + 1][0] = r2; bfr[pr * 2 + 1][1] = r3;
            }
#pragma unroll
            for (int im = 0; im < 4; im++)
#pragma unroll
                for (int jn = 0; jn < 8; jn++)
                    MMA16816(acc[im][jn], afr[im], bfr[jn]);
        }
        // (no bottom barrier: next-iteration stage writes are fenced by the
        //  top barrier of iteration kt+1, which follows all reads of kt)
    }

    // ---------------- fused epilogue ----------------
    const int base0 = nbase + wn * 64;
    const int hA = base0 / 96;
    float ps[4][2][2];
    float pd[4][2][2];
#pragma unroll
    for (int a = 0; a < 4; a++)
#pragma unroll
        for (int b = 0; b < 2; b++)
#pragma unroll
            for (int c = 0; c < 2; c++) { ps[a][b][c] = 0.f; pd[a][b][c] = 0.f; }

#pragma unroll
    for (int jn = 0; jn < 8; jn++) {
        int col = base0 + jn * 8 + (lane & 3) * 2;
        int slot = (col / 96) - hA;
        float as0 = __ldg(attS + col), as1 = __ldg(attS + col + 1);
        float ad0 = __ldg(attD + col), ad1 = __ldg(attD + col + 1);
#pragma unroll
        for (int im = 0; im < 4; im++) {
            int r0 = mbase + wm * 64 + im * 16 + (lane >> 2);
            if (r0 < NN)
                *(float2*)&d_g[(size_t)r0 * HIDD + col] =
                    make_float2(acc[im][jn][0], acc[im][jn][1]);
            if (r0 + 8 < NN)
                *(float2*)&d_g[(size_t)(r0 + 8) * HIDD + col] =
                    make_float2(acc[im][jn][2], acc[im][jn][3]);
            ps[im][0][slot] += acc[im][jn][0] * as0 + acc[im][jn][1] * as1;
            pd[im][0][slot] += acc[im][jn][0] * ad0 + acc[im][jn][1] * ad1;
            ps[im][1][slot] += acc[im][jn][2] * as0 + acc[im][jn][3] * as1;
            pd[im][1][slot] += acc[im][jn][2] * ad0 + acc[im][jn][3] * ad1;
        }
    }
#pragma unroll
    for (int im = 0; im < 4; im++)
#pragma unroll
        for (int rh = 0; rh < 2; rh++)
#pragma unroll
            for (int sl = 0; sl < 2; sl++) {
                float vs = ps[im][rh][sl], vd = pd[im][rh][sl];
                vs += __shfl_xor_sync(0xffffffffu, vs, 1);
                vs += __shfl_xor_sync(0xffffffffu, vs, 2);
                vd += __shfl_xor_sync(0xffffffffu, vd, 1);
                vd += __shfl_xor_sync(0xffffffffu, vd, 2);
                if ((lane & 3) == 0) {
                    int row = mbase + wm * 64 + im * 16 + (lane >> 2) + rh * 8;
                    int h = hA + sl;
                    if (row < NN && h < NH) {
                        atomicAdd(&asb[row * 8 + h], vs);
                        atomicAdd(&adb[row * 8 + h], vd);
                    }
                }
            }
}

// =====================================================================
// Attention: per-warp softmax + pair-balanced channel-split gather.
// block = 256 = 8 nodes. Zeros the NEXT layer's as/ad buffers.
// =====================================================================
__global__ __launch_bounds__(256) void k_attn(
    const float* __restrict__ cas, const float* __restrict__ cad,
    float* __restrict__ nas, float* __restrict__ nad,
    const float* __restrict__ bias, int write_h)
{
    __shared__ float ebuf[8][MAXD * 8];   // 16 KB alpha cache
    __shared__ float smx[8][8];
    __shared__ float sinv[8][8];

    const int warp = threadIdx.x >> 5, lane = threadIdx.x & 31;
    const int blkbase = blockIdx.x * 8;
    const int n = blkbase + warp;

    if (lane < 8) { nas[n * 8 + lane] = 0.f; nad[n * 8 + lane] = 0.f; }

    const int beg = d_rowptr[n], end = d_rowptr[n + 1];
    const int deg = end - beg;

    const float4* adp = (const float4*)(cad + n * 8);
    float4 ad0 = adp[0], ad1 = adp[1];
    float ad[8] = {ad0.x, ad0.y, ad0.z, ad0.w, ad1.x, ad1.y, ad1.z, ad1.w};

    // ---------- phase 1: per-warp softmax for own node ----------
    float mx[8];
#pragma unroll
    for (int h = 0; h < 8; h++) mx[h] = -1e30f;
    if (deg <= MAXD) {
#pragma unroll
        for (int it = 0; it < 2; it++) {
            int le = it * 32 + lane;
            if (le < deg) {
                int s = d_csrsrc[beg + le];
                const float4* ap = (const float4*)(cas + s * 8);
                float4 a0 = ap[0], a1 = ap[1];
                float ev[8] = {a0.x, a0.y, a0.z, a0.w, a1.x, a1.y, a1.z, a1.w};
#pragma unroll
                for (int h = 0; h < 8; h++) {
                    float e = ev[h] + ad[h];
                    e = e > 0.f ? e : 0.2f * e;
                    ebuf[warp][le * 8 + h] = e;
                    mx[h] = fmaxf(mx[h], e);
                }
            }
        }
    } else {
        for (int i0 = beg + lane; i0 < end; i0 += 32) {
            int s = d_csrsrc[i0];
            const float4* ap = (const float4*)(cas + s * 8);
            float4 a0 = ap[0], a1 = ap[1];
            float ev[8] = {a0.x, a0.y, a0.z, a0.w, a1.x, a1.y, a1.z, a1.w};
#pragma unroll
            for (int h = 0; h < 8; h++) {
                float e = ev[h] + ad[h];
                e = e > 0.f ? e : 0.2f * e;
                mx[h] = fmaxf(mx[h], e);
            }
        }
    }
#pragma unroll
    for (int h = 0; h < 8; h++)
        for (int off = 16; off; off >>= 1)
            mx[h] = fmaxf(mx[h], __shfl_xor_sync(0xffffffffu, mx[h], off));
    __syncwarp();

    float sm[8];
#pragma unroll
    for (int h = 0; h < 8; h++) sm[h] = 0.f;
    if (deg <= MAXD) {
#pragma unroll
        for (int it = 0; it < 2; it++) {
            int le = it * 32 + lane;
            if (le < deg) {
#pragma unroll
                for (int h = 0; h < 8; h++) {
                    float p = __expf(ebuf[warp][le * 8 + h] - mx[h]);
                    ebuf[warp][le * 8 + h] = p;
                    sm[h] += p;
                }
            }
        }
    } else {
        for (int i0 = beg + lane; i0 < end; i0 += 32) {
            int s = d_csrsrc[i0];
            const float4* ap = (const float4*)(cas + s * 8);
            float4 a0 = ap[0], a1 = ap[1];
            float ev[8] = {a0.x, a0.y, a0.z, a0.w, a1.x, a1.y, a1.z, a1.w};
#pragma unroll
            for (int h = 0; h < 8; h++) {
                float e = ev[h] + ad[h];
                e = e > 0.f ? e : 0.2f * e;
                sm[h] += __expf(e - mx[h]);
            }
        }
    }
#pragma unroll
    for (int h = 0; h < 8; h++)
        for (int off = 16; off; off >>= 1)
            sm[h] += __shfl_xor_sync(0xffffffffu, sm[h], off);
    float inv[8];
#pragma unroll
    for (int h = 0; h < 8; h++) inv[h] = 1.f / (sm[h] + 1e-16f);
    if (lane < 8) { smx[warp][lane] = mx[lane]; sinv[warp][lane] = inv[lane]; }
    __syncwarp();

    if (deg <= MAXD) {
#pragma unroll
        for (int it = 0; it < 2; it++) {
            int le = it * 32 + lane;
            if (le < deg) {
#pragma unroll
                for (int h = 0; h < 8; h++)
                    ebuf[warp][le * 8 + h] *= inv[h];
            }
        }
    }
    __syncthreads();

    // ---------- phase 2: pair-balanced gather ----------
    const int pw = warp & 1;
    const int q0 = warp & ~1;
    int slot_t[3], head_t[3], j4_t[3];
#pragma unroll
    for (int t = 0; t < 3; t++) {
        slot_t[t] = pw * 3 + t;
        j4_t[t] = lane + 32 * slot_t[t];
        head_t[t] = j4_t[t] / 24;
    }

#pragma unroll
    for (int qi = 0; qi < 2; qi++) {
        int q = q0 + qi;
        int nq = blkbase + q;
        int bq = d_rowptr[nq], eq = d_rowptr[nq + 1];
        int dq = eq - bq;

        float4 acc4[3];
#pragma unroll
        for (int t = 0; t < 3; t++) acc4[t] = make_float4(0.f, 0.f, 0.f, 0.f);

        if (dq <= MAXD) {
            int le = 0;
            for (; le + 4 <= dq; le += 4) {
                int s0 = d_csrsrc[bq + le];
                int s1 = d_csrsrc[bq + le + 1];
                int s2 = d_csrsrc[bq + le + 2];
                int s3 = d_csrsrc[bq + le + 3];
                const float4* g0 = (const float4*)(d_g + (size_t)s0 * HIDD);
                const float4* g1 = (const float4*)(d_g + (size_t)s1 * HIDD);
                const float4* g2 = (const float4*)(d_g + (size_t)s2 * HIDD);
                const float4* g3 = (const float4*)(d_g + (size_t)s3 * HIDD);
#pragma unroll
                for (int t = 0; t < 3; t++) {
                    int j4 = j4_t[t], hh = head_t[t];
                    float a0 = ebuf[q][le * 8 + hh];
                    float a1 = ebuf[q][(le + 1) * 8 + hh];
                    float a2 = ebuf[q][(le + 2) * 8 + hh];
                    float a3 = ebuf[q][(le + 3) * 8 + hh];
                    float4 v0 = g0[j4], v1 = g1[j4], v2 = g2[j4], v3 = g3[j4];
                    acc4[t].x += a0 * v0.x + a1 * v1.x + a2 * v2.x + a3 * v3.x;
                    acc4[t].y += a0 * v0.y + a1 * v1.y + a2 * v2.y + a3 * v3.y;
                    acc4[t].z += a0 * v0.z + a1 * v1.z + a2 * v2.z + a3 * v3.z;
                    acc4[t].w += a0 * v0.w + a1 * v1.w + a2 * v2.w + a3 * v3.w;
                }
            }
            for (; le < dq; le++) {
                int s0 = d_csrsrc[bq + le];
                const float4* g0 = (const float4*)(d_g + (size_t)s0 * HIDD);
#pragma unroll
                for (int t = 0; t < 3; t++) {
                    float a0 = ebuf[q][le * 8 + head_t[t]];
                    float4 v0 = g0[j4_t[t]];
                    acc4[t].x += a0 * v0.x;
                    acc4[t].y += a0 * v0.y;
                    acc4[t].z += a0 * v0.z;
                    acc4[t].w += a0 * v0.w;
                }
            }
        } else {
            float adq[3], mxq[3], invq[3];
#pragma unroll
            for (int t = 0; t < 3; t++) {
                adq[t] = __ldg(cad + nq * 8 + head_t[t]);
                mxq[t] = smx[q][head_t[t]];
                invq[t] = sinv[q][head_t[t]];
            }
            for (int le = 0; le < dq; le++) {
                int s0 = d_csrsrc[bq + le];
                const float4* g0 = (const float4*)(d_g + (size_t)s0 * HIDD);
#pragma unroll
                for (int t = 0; t < 3; t++) {
                    float e = __ldg(cas + s0 * 8 + head_t[t]) + adq[t];
                    e = e > 0.f ? e : 0.2f * e;
                    float a0 = __expf(e - mxq[t]) * invq[t];
                    float4 v0 = g0[j4_t[t]];
                    acc4[t].x += a0 * v0.x;
                    acc4[t].y += a0 * v0.y;
                    acc4[t].z += a0 * v0.z;
                    acc4[t].w += a0 * v0.w;
                }
            }
        }

#pragma unroll
        for (int t = 0; t < 3; t++) {
            int j = 4 * j4_t[t];
            float4 b4 = *(const float4*)(bias + j);
            float4 v = acc4[t];
            v.x = fmaxf(v.x + b4.x, 0.f);
            v.y = fmaxf(v.y + b4.y, 0.f);
            v.z = fmaxf(v.z + b4.z, 0.f);
            v.w = fmaxf(v.w + b4.w, 0.f);
            if (write_h) *(float4*)&d_h[(size_t)nq * HIDD + j] = v;
            write_split4(nq, j, v);
        }
    }
}

// ---------------- pooling / fc ----------------
__global__ void k_pool() {
    int b = blockIdx.x;
    int j = blockIdx.y * 256 + threadIdx.x;
    int beg = d_gstart[b], end = d_gstart[b + 1];
    float s = 0.f;
    for (int n = beg; n < end; n++) s += d_h[(size_t)n * HIDD + j];
    float cnt = (float)(end - beg);
    d_pool[b * HIDD + j] = s / fmaxf(cnt, 1.0f);
}

__global__ void k_fc(const float* __restrict__ W, const float* __restrict__ b,
                     float* __restrict__ out) {
    int id = blockIdx.x * 256 + threadIdx.x;
    if (id >= NGB * EMB) return;
    int bb = id / EMB, k = id % EMB;
    float s = b[k];
    for (int j = 0; j < HIDD; j++) s += d_pool[bb * HIDD + j] * W[j * EMB + k];
    out[id] = s;
}

// ---------------- host launch ----------------
extern "C" void kernel_launch(void* const* d_in, const int* in_sizes, int n_in,
                              void* d_out, int out_size) {
    const float* x     = (const float*)d_in[0];
    const int*   ei    = (const int*)d_in[1];
    const int*   batch = (const int*)d_in[2];
    const float* projW = (const float*)d_in[3];
    const float* projb = (const float*)d_in[4];
    const float* convW = (const float*)d_in[5];
    const float* attS  = (const float*)d_in[6];
    const float* attD  = (const float*)d_in[7];
    const float* convb = (const float*)d_in[8];
    const float* fcW   = (const float*)d_in[9];
    const float* fcb   = (const float*)d_in[10];
    float* out = (float*)d_out;

    static bool attr_set = false;
    if (!attr_set) {
        cudaFuncSetAttribute(k_gemm_hmma, cudaFuncAttributeMaxDynamicSharedMemorySize, SMEM_GEMM);
        attr_set = true;
    }

    void* pW = nullptr;
    cudaGetSymbolAddress(&pW, d_WcatT);
    const __nv_bfloat16* Wcat = (const __nv_bfloat16*)pW;
    void *pa0, *pd0, *pa1, *pd1;
    cudaGetSymbolAddress(&pa0, d_as0);
    cudaGetSymbolAddress(&pd0, d_ad0);
    cudaGetSymbolAddress(&pa1, d_as1);
    cudaGetSymbolAddress(&pd1, d_ad1);
    float* asb[2] = {(float*)pa0, (float*)pa1};
    float* adb[2] = {(float*)pd0, (float*)pd1};

    k_zero_deg<<<(NN + 255) / 256, 256>>>();
    k_hist<<<(EA + 255) / 256, 256>>>(ei);
    k_scan<<<1, 1024>>>();
    k_scatter<<<(EA + 255) / 256, 256>>>(ei);
    k_gstart<<<(NN + 255) / 256, 256>>>(batch);
    k_proj<<<(NN * HIDD + 255) / 256, 256>>>(x, projW, projb);
    k_split_w<<<(NL * HIDD * HIDD + 255) / 256, 256>>>(convW);
    k_zero_asd0<<<(NN * NH + 255) / 256, 256>>>();

    for (int l = 0; l < NL; l++) {
        int cur = l & 1, nxt = cur ^ 1;
        dim3 gg(HIDD / 256, (NN + 127) / 128);   // 3 x 157
        k_gemm_hmma<<<gg, 256, SMEM_GEMM>>>(Wcat + (size_t)l * HIDD * KCAT,
                                            attS + l * HIDD, attD + l * HIDD,
                                            asb[cur], adb[cur]);
        k_attn<<<NN / 8, 256>>>(asb[cur], adb[cur], asb[nxt], adb[nxt],
                                convb + l * HIDD, (l == NL - 1) ? 1 : 0);
    }

    dim3 gp(NGB, 3);
    k_pool<<<gp, 256>>>();
    k_fc<<<(NGB * EMB + 255) / 256, 256>>>(fcW, fcb, out);
}

// round 13
// speedup vs baseline: 1.1591x; 1.0723x over previous
#include <cuda_runtime.h>
#include <cuda_bf16.h>
#include <cstdint>

#define NN 20000
#define EE 320000
#define EA 340000      // E + N self loops
#define HIDD 768
#define NH 8
#define NC 96
#define NL 16
#define NGB 16
#define EMB 512
#define KCAT 2304      // 3 * HIDD (bf16 split: hi*hi + lo*hi + hi*lo)
#define MAXD 64        // smem softmax cache cap (recompute path beyond)

// ---------------- scratch (device globals; no allocations) ----------------
__device__ float d_h[NN * HIDD];
__device__ float d_g[NN * HIDD];
__device__ float d_as0[NN * NH];
__device__ float d_ad0[NN * NH];
__device__ float d_as1[NN * NH];
__device__ float d_ad1[NN * NH];
__device__ int   d_deg[NN];
__device__ int   d_rowptr[NN + 1];
__device__ int   d_cursor[NN];
__device__ int   d_csrsrc[EA];
__device__ int   d_gstart[NGB + 1];
__device__ float d_pool[NGB * HIDD];
__device__ __nv_bfloat16 d_Acat[(size_t)NN * KCAT];           // h split, [N, 2304]
__device__ __nv_bfloat16 d_WcatT[(size_t)NL * HIDD * KCAT];   // W^T split, [L, 768n, 2304k]

// ---------------- CSR build ----------------
__global__ void k_zero_deg() {
    int i = blockIdx.x * 256 + threadIdx.x;
    if (i < NN) d_deg[i] = 0;
}

__global__ void k_hist(const int* __restrict__ ei) {
    int i = blockIdx.x * 256 + threadIdx.x;
    if (i >= EA) return;
    int dst = (i < EE) ? ei[EE + i] : (i - EE);
    atomicAdd(&d_deg[dst], 1);
}

__global__ void k_scan() {
    __shared__ int sdata[1024];
    __shared__ int carry;
    int tid = threadIdx.x;
    if (tid == 0) { carry = 0; d_rowptr[0] = 0; }
    __syncthreads();
    for (int base = 0; base < NN; base += 1024) {
        int i = base + tid;
        int v = (i < NN) ? d_deg[i] : 0;
        sdata[tid] = v;
        __syncthreads();
        for (int off = 1; off < 1024; off <<= 1) {
            int t = (tid >= off) ? sdata[tid - off] : 0;
            __syncthreads();
            sdata[tid] += t;
            __syncthreads();
        }
        int incl = sdata[tid] + carry;
        if (i < NN) d_rowptr[i + 1] = incl;
        __syncthreads();
        if (tid == 1023) carry = incl;
        __syncthreads();
    }
    for (int i = tid; i < NN; i += 1024) d_cursor[i] = d_rowptr[i];
}

__global__ void k_scatter(const int* __restrict__ ei) {
    int i = blockIdx.x * 256 + threadIdx.x;
    if (i >= EA) return;
    int src, dst;
    if (i < EE) { src = ei[i]; dst = ei[EE + i]; }
    else        { src = i - EE; dst = src; }
    int slot = atomicAdd(&d_cursor[dst], 1);
    d_csrsrc[slot] = src;
}

__global__ void k_gstart(const int* __restrict__ batch) {
    int n = blockIdx.x * 256 + threadIdx.x;
    if (n >= NN) return;
    int b = batch[n];
    if (n == 0) {
        for (int bb = 0; bb <= b; bb++) d_gstart[bb] = 0;
    } else {
        int pb = batch[n - 1];
        if (pb != b) for (int bb = pb + 1; bb <= b; bb++) d_gstart[bb] = n;
    }
    if (n == NN - 1) {
        for (int bb = b + 1; bb <= NGB; bb++) d_gstart[bb] = NN;
    }
}

__global__ void k_zero_asd0() {
    int i = blockIdx.x * 256 + threadIdx.x;
    if (i < NN * NH) { d_as0[i] = 0.f; d_ad0[i] = 0.f; }
}

// ---------------- split write helpers ----------------
__device__ __forceinline__ void write_split(int n, int k, float v) {
    __nv_bfloat16 hi = __float2bfloat16(v);
    __nv_bfloat16 lo = __float2bfloat16(v - __bfloat162float(hi));
    size_t base = (size_t)n * KCAT;
    d_Acat[base + k]            = hi;
    d_Acat[base + HIDD + k]     = lo;
    d_Acat[base + 2 * HIDD + k] = hi;
}

__device__ __forceinline__ void write_split4(int n, int j, float4 v) {
    float vv[4] = {v.x, v.y, v.z, v.w};
    __nv_bfloat162 hp[2], lp[2];
#pragma unroll
    for (int q = 0; q < 2; q++) {
        __nv_bfloat16 h0 = __float2bfloat16(vv[2 * q]);
        __nv_bfloat16 h1 = __float2bfloat16(vv[2 * q + 1]);
        __nv_bfloat16 l0 = __float2bfloat16(vv[2 * q]     - __bfloat162float(h0));
        __nv_bfloat16 l1 = __float2bfloat16(vv[2 * q + 1] - __bfloat162float(h1));
        hp[q] = __nv_bfloat162(h0, h1);
        lp[q] = __nv_bfloat162(l0, l1);
    }
    size_t base = (size_t)n * KCAT;
    __nv_bfloat162* p0 = (__nv_bfloat162*)&d_Acat[base + j];
    __nv_bfloat162* p1 = (__nv_bfloat162*)&d_Acat[base + HIDD + j];
    __nv_bfloat162* p2 = (__nv_bfloat162*)&d_Acat[base + 2 * HIDD + j];
    p0[0] = hp[0]; p0[1] = hp[1];
    p1[0] = lp[0]; p1[1] = lp[1];
    p2[0] = hp[0]; p2[1] = hp[1];
}

// ---------------- input projection (split only) ----------------
__global__ void k_proj(const float* __restrict__ x, const float* __restrict__ W,
                       const float* __restrict__ b) {
    int id = blockIdx.x * 256 + threadIdx.x;
    if (id >= NN * HIDD) return;
    int n = id / HIDD, j = id % HIDD;
    float s = b[j];
#pragma unroll
    for (int f = 0; f < 5; f++) s += x[n * 5 + f] * W[f * HIDD + j];
    write_split(n, j, s);
}

// ---------------- bf16 split: weights (once) ----------------
__global__ void k_split_w(const float* __restrict__ convW) {
    int id = blockIdx.x * 256 + threadIdx.x;
    if (id >= NL * HIDD * HIDD) return;
    int l = id / (HIDD * HIDD);
    int rem = id % (HIDD * HIDD);
    int k = rem / HIDD, n = rem % HIDD;
    float v = convW[id];
    __nv_bfloat16 hi = __float2bfloat16(v);
    __nv_bfloat16 lo = __float2bfloat16(v - __bfloat162float(hi));
    size_t base = ((size_t)l * HIDD + n) * KCAT;
    d_WcatT[base + k]            = hi;
    d_WcatT[base + HIDD + k]     = hi;
    d_WcatT[base + 2 * HIDD + k] = lo;
}

// =====================================================================
// HMMA GEMM: 128x128 CTA tile, 128 threads (2m x 2n warps of 64x64),
// BK=64, 3-stage cp.async, 2 CTAs/SM. Fused asd epilogue.
// =====================================================================
#define BK 64
#define STAGES 3
#define STG_A 16384
#define STG_B 16384
#define SMEM_GEMM (STAGES * (STG_A + STG_B))   // 98304

__device__ __forceinline__ uint32_t swz(uint32_t b) { return b ^ ((b >> 3) & 0x70); }

__device__ __forceinline__ uint32_t smem_u32(const void* p) {
    uint32_t a;
    asm("{ .reg .u64 t; cvta.to.shared.u64 t, %1; cvt.u32.u64 %0, t; }" : "=r"(a) : "l"(p));
    return a;
}

#define CP_ASYNC(dst, src, sz) \
    asm volatile("cp.async.cg.shared.global [%0], [%1], 16, %2;" \
        :: "r"(dst), "l"(src), "r"(sz))
#define CP_COMMIT() asm volatile("cp.async.commit_group;")
#define CP_WAIT1()  asm volatile("cp.async.wait_group 1;")

#define LDMX4(r0, r1, r2, r3, a) \
    asm volatile("ldmatrix.sync.aligned.m8n8.x4.shared.b16 {%0,%1,%2,%3}, [%4];" \
        : "=r"(r0), "=r"(r1), "=r"(r2), "=r"(r3) : "r"(a))

#define MMA16816(d, a, b) \
    asm volatile("mma.sync.aligned.m16n8k16.row.col.f32.bf16.bf16.f32 " \
        "{%0,%1,%2,%3}, {%4,%5,%6,%7}, {%8,%9}, {%0,%1,%2,%3};" \
        : "+f"((d)[0]), "+f"((d)[1]), "+f"((d)[2]), "+f"((d)[3]) \
        : "r"((a)[0]), "r"((a)[1]), "r"((a)[2]), "r"((a)[3]), "r"((b)[0]), "r"((b)[1]))

__global__ __launch_bounds__(128, 2) void k_gemm_hmma(
    const __nv_bfloat16* __restrict__ Wl,
    const float* __restrict__ attS, const float* __restrict__ attD,
    float* __restrict__ asb, float* __restrict__ adb)
{
    extern __shared__ __align__(128) char smem[];
    uint32_t sA = smem_u32(smem);
    uint32_t sB = sA + STAGES * STG_A;

    const int tid = threadIdx.x;
    const int lane = tid & 31, warp = tid >> 5;
    const int wm = warp & 1, wn = warp >> 1;         // 2 m-warps x 2 n-warps
    const int mtile = blockIdx.y, ntile = blockIdx.x;
    const int mbase = mtile * 128;
    const int nbase = ntile * 128;

    const __nv_bfloat16* Ag = d_Acat;

    auto issue_stage = [&](int kt, int st) {
        int k0 = kt * BK;
        uint32_t a_dst = sA + st * STG_A;
#pragma unroll
        for (int it = 0; it < 8; it++) {             // A: 1024 chunks / 128 thr
            int id = it * 128 + tid;
            int row = id >> 3, ck = id & 7;
            int gr = mbase + row;
            const __nv_bfloat16* srcA = Ag + (size_t)gr * KCAT + k0 + ck * 8;
            CP_ASYNC(a_dst + swz(row * 128 + ck * 16), srcA, (gr < NN) ? 16 : 0);
        }
        uint32_t b_dst = sB + st * STG_B;
#pragma unroll
        for (int it = 0; it < 8; it++) {             // B: 1024 chunks
            int id = it * 128 + tid;
            int row = id >> 3, ck = id & 7;
            const __nv_bfloat16* srcB = Wl + (size_t)(nbase + row) * KCAT + k0 + ck * 8;
            CP_ASYNC(b_dst + swz(row * 128 + ck * 16), srcB, 16);
        }
        CP_COMMIT();
    };

    issue_stage(0, 0);
    issue_stage(1, 1);

    float acc[4][8][4];
#pragma unroll
    for (int i = 0; i < 4; i++)
#pragma unroll
        for (int j = 0; j < 8; j++)
#pragma unroll
            for (int c = 0; c < 4; c++) acc[i][j][c] = 0.f;

    const int NKT = KCAT / BK;
    for (int kt = 0; kt < NKT; kt++) {
        CP_WAIT1();
        __syncthreads();
        if (kt + 2 < NKT) issue_stage(kt + 2, (kt + 2) % STAGES);
        else CP_COMMIT();

        int st = kt % STAGES;
        uint32_t aS = sA + st * STG_A;
        uint32_t bS = sB + st * STG_B;

#pragma unroll
        for (int ks = 0; ks < 4; ks++) {
            uint32_t afr[4][4];
#pragma unroll
            for (int im = 0; im < 4; im++) {
                int row = wm * 64 + im * 16 + (lane & 15);
                int kk = ks * 16 + (lane >> 4) * 8;
                LDMX4(afr[im][0], afr[im][1], afr[im][2], afr[im][3],
                      aS + swz(row * 128 + kk * 2));
            }
            uint32_t bfr[8][2];
#pragma unroll
            for (int pr = 0; pr < 4; pr++) {
                int nrow = wn * 64 + pr * 16 + (lane & 7) + ((lane & 16) ? 8 : 0);
                int kk = ks * 16 + ((lane & 8) ? 8 : 0);
                uint32_t r0, r1, r2, r3;
                LDMX4(r0, r1, r2, r3, bS + swz(nrow * 128 + kk * 2));
                bfr[pr * 2][0] = r0;     bfr[pr * 2][1] = r1;
                bfr[pr * 2 + 1][0] = r2; bfr[pr * 2 + 1][1] = r3;
            }
#pragma unroll
            for (int im = 0; im < 4; im++)
#pragma unroll
                for (int jn = 0; jn < 8; jn++)
                    MMA16816(acc[im][jn], afr[im], bfr[jn]);
        }
        // single barrier per kt (bottom barrier proven redundant in R12)
    }

    // ---------------- fused epilogue ----------------
    const int base0 = nbase + wn * 64;
    const int hA = base0 / 96;
    float ps[4][2][2];
    float pd[4][2][2];
#pragma unroll
    for (int a = 0; a < 4; a++)
#pragma unroll
        for (int b = 0; b < 2; b++)
#pragma unroll
            for (int c = 0; c < 2; c++) { ps[a][b][c] = 0.f; pd[a][b][c] = 0.f; }

#pragma unroll
    for (int jn = 0; jn < 8; jn++) {
        int col = base0 + jn * 8 + (lane & 3) * 2;
        int slot = (col / 96) - hA;
        float as0 = __ldg(attS + col), as1 = __ldg(attS + col + 1);
        float ad0 = __ldg(attD + col), ad1 = __ldg(attD + col + 1);
#pragma unroll
        for (int im = 0; im < 4; im++) {
            int r0 = mbase + wm * 64 + im * 16 + (lane >> 2);
            if (r0 < NN)
                *(float2*)&d_g[(size_t)r0 * HIDD + col] =
                    make_float2(acc[im][jn][0], acc[im][jn][1]);
            if (r0 + 8 < NN)
                *(float2*)&d_g[(size_t)(r0 + 8) * HIDD + col] =
                    make_float2(acc[im][jn][2], acc[im][jn][3]);
            ps[im][0][slot] += acc[im][jn][0] * as0 + acc[im][jn][1] * as1;
            pd[im][0][slot] += acc[im][jn][0] * ad0 + acc[im][jn][1] * ad1;
            ps[im][1][slot] += acc[im][jn][2] * as0 + acc[im][jn][3] * as1;
            pd[im][1][slot] += acc[im][jn][2] * ad0 + acc[im][jn][3] * ad1;
        }
    }
#pragma unroll
    for (int im = 0; im < 4; im++)
#pragma unroll
        for (int rh = 0; rh < 2; rh++)
#pragma unroll
            for (int sl = 0; sl < 2; sl++) {
                float vs = ps[im][rh][sl], vd = pd[im][rh][sl];
                vs += __shfl_xor_sync(0xffffffffu, vs, 1);
                vs += __shfl_xor_sync(0xffffffffu, vs, 2);
                vd += __shfl_xor_sync(0xffffffffu, vd, 1);
                vd += __shfl_xor_sync(0xffffffffu, vd, 2);
                if ((lane & 3) == 0) {
                    int row = mbase + wm * 64 + im * 16 + (lane >> 2) + rh * 8;
                    int h = hA + sl;
                    if (row < NN && h < NH) {
                        atomicAdd(&asb[row * 8 + h], vs);
                        atomicAdd(&adb[row * 8 + h], vd);
                    }
                }
            }
}

// =====================================================================
// Attention: per-warp softmax + pair-balanced channel-split gather.
// block = 256 = 8 nodes. Zeros the NEXT layer's as/ad buffers.
// =====================================================================
__global__ __launch_bounds__(256) void k_attn(
    const float* __restrict__ cas, const float* __restrict__ cad,
    float* __restrict__ nas, float* __restrict__ nad,
    const float* __restrict__ bias, int write_h)
{
    __shared__ float ebuf[8][MAXD * 8];   // 16 KB alpha cache
    __shared__ float smx[8][8];
    __shared__ float sinv[8][8];

    const int warp = threadIdx.x >> 5, lane = threadIdx.x & 31;
    const int blkbase = blockIdx.x * 8;
    const int n = blkbase + warp;

    if (lane < 8) { nas[n * 8 + lane] = 0.f; nad[n * 8 + lane] = 0.f; }

    const int beg = d_rowptr[n], end = d_rowptr[n + 1];
    const int deg = end - beg;

    const float4* adp = (const float4*)(cad + n * 8);
    float4 ad0 = adp[0], ad1 = adp[1];
    float ad[8] = {ad0.x, ad0.y, ad0.z, ad0.w, ad1.x, ad1.y, ad1.z, ad1.w};

    // ---------- phase 1: per-warp softmax for own node ----------
    float mx[8];
#pragma unroll
    for (int h = 0; h < 8; h++) mx[h] = -1e30f;
    if (deg <= MAXD) {
#pragma unroll
        for (int it = 0; it < 2; it++) {
            int le = it * 32 + lane;
            if (le < deg) {
                int s = d_csrsrc[beg + le];
                const float4* ap = (const float4*)(cas + s * 8);
                float4 a0 = ap[0], a1 = ap[1];
                float ev[8] = {a0.x, a0.y, a0.z, a0.w, a1.x, a1.y, a1.z, a1.w};
#pragma unroll
                for (int h = 0; h < 8; h++) {
                    float e = ev[h] + ad[h];
                    e = e > 0.f ? e : 0.2f * e;
                    ebuf[warp][le * 8 + h] = e;
                    mx[h] = fmaxf(mx[h], e);
                }
            }
        }
    } else {
        for (int i0 = beg + lane; i0 < end; i0 += 32) {
            int s = d_csrsrc[i0];
            const float4* ap = (const float4*)(cas + s * 8);
            float4 a0 = ap[0], a1 = ap[1];
            float ev[8] = {a0.x, a0.y, a0.z, a0.w, a1.x, a1.y, a1.z, a1.w};
#pragma unroll
            for (int h = 0; h < 8; h++) {
                float e = ev[h] + ad[h];
                e = e > 0.f ? e : 0.2f * e;
                mx[h] = fmaxf(mx[h], e);
            }
        }
    }
#pragma unroll
    for (int h = 0; h < 8; h++)
        for (int off = 16; off; off >>= 1)
            mx[h] = fmaxf(mx[h], __shfl_xor_sync(0xffffffffu, mx[h], off));
    __syncwarp();

    float sm[8];
#pragma unroll
    for (int h = 0; h < 8; h++) sm[h] = 0.f;
    if (deg <= MAXD) {
#pragma unroll
        for (int it = 0; it < 2; it++) {
            int le = it * 32 + lane;
            if (le < deg) {
#pragma unroll
                for (int h = 0; h < 8; h++) {
                    float p = __expf(ebuf[warp][le * 8 + h] - mx[h]);
                    ebuf[warp][le * 8 + h] = p;
                    sm[h] += p;
                }
            }
        }
    } else {
        for (int i0 = beg + lane; i0 < end; i0 += 32) {
            int s = d_csrsrc[i0];
            const float4* ap = (const float4*)(cas + s * 8);
            float4 a0 = ap[0], a1 = ap[1];
            float ev[8] = {a0.x, a0.y, a0.z, a0.w, a1.x, a1.y, a1.z, a1.w};
#pragma unroll
            for (int h = 0; h < 8; h++) {
                float e = ev[h] + ad[h];
                e = e > 0.f ? e : 0.2f * e;
                sm[h] += __expf(e - mx[h]);
            }
        }
    }
#pragma unroll
    for (int h = 0; h < 8; h++)
        for (int off = 16; off; off >>= 1)
            sm[h] += __shfl_xor_sync(0xffffffffu, sm[h], off);
    float inv[8];
#pragma unroll
    for (int h = 0; h < 8; h++) inv[h] = 1.f / (sm[h] + 1e-16f);
    if (lane < 8) { smx[warp][lane] = mx[lane]; sinv[warp][lane] = inv[lane]; }
    __syncwarp();

    if (deg <= MAXD) {
#pragma unroll
        for (int it = 0; it < 2; it++) {
            int le = it * 32 + lane;
            if (le < deg) {
#pragma unroll
                for (int h = 0; h < 8; h++)
                    ebuf[warp][le * 8 + h] *= inv[h];
            }
        }
    }
    __syncthreads();

    // ---------- phase 2: pair-balanced gather ----------
    const int pw = warp & 1;
    const int q0 = warp & ~1;
    int slot_t[3], head_t[3], j4_t[3];
#pragma unroll
    for (int t = 0; t < 3; t++) {
        slot_t[t] = pw * 3 + t;
        j4_t[t] = lane + 32 * slot_t[t];
        head_t[t] = j4_t[t] / 24;
    }

#pragma unroll
    for (int qi = 0; qi < 2; qi++) {
        int q = q0 + qi;
        int nq = blkbase + q;
        int bq = d_rowptr[nq], eq = d_rowptr[nq + 1];
        int dq = eq - bq;

        float4 acc4[3];
#pragma unroll
        for (int t = 0; t < 3; t++) acc4[t] = make_float4(0.f, 0.f, 0.f, 0.f);

        if (dq <= MAXD) {
            int le = 0;
            for (; le + 4 <= dq; le += 4) {
                int s0 = d_csrsrc[bq + le];
                int s1 = d_csrsrc[bq + le + 1];
                int s2 = d_csrsrc[bq + le + 2];
                int s3 = d_csrsrc[bq + le + 3];
                const float4* g0 = (const float4*)(d_g + (size_t)s0 * HIDD);
                const float4* g1 = (const float4*)(d_g + (size_t)s1 * HIDD);
                const float4* g2 = (const float4*)(d_g + (size_t)s2 * HIDD);
                const float4* g3 = (const float4*)(d_g + (size_t)s3 * HIDD);
#pragma unroll
                for (int t = 0; t < 3; t++) {
                    int j4 = j4_t[t], hh = head_t[t];
                    float a0 = ebuf[q][le * 8 + hh];
                    float a1 = ebuf[q][(le + 1) * 8 + hh];
                    float a2 = ebuf[q][(le + 2) * 8 + hh];
                    float a3 = ebuf[q][(le + 3) * 8 + hh];
                    float4 v0 = g0[j4], v1 = g1[j4], v2 = g2[j4], v3 = g3[j4];
                    acc4[t].x += a0 * v0.x + a1 * v1.x + a2 * v2.x + a3 * v3.x;
                    acc4[t].y += a0 * v0.y + a1 * v1.y + a2 * v2.y + a3 * v3.y;
                    acc4[t].z += a0 * v0.z + a1 * v1.z + a2 * v2.z + a3 * v3.z;
                    acc4[t].w += a0 * v0.w + a1 * v1.w + a2 * v2.w + a3 * v3.w;
                }
            }
            for (; le < dq; le++) {
                int s0 = d_csrsrc[bq + le];
                const float4* g0 = (const float4*)(d_g + (size_t)s0 * HIDD);
#pragma unroll
                for (int t = 0; t < 3; t++) {
                    float a0 = ebuf[q][le * 8 + head_t[t]];
                    float4 v0 = g0[j4_t[t]];
                    acc4[t].x += a0 * v0.x;
                    acc4[t].y += a0 * v0.y;
                    acc4[t].z += a0 * v0.z;
                    acc4[t].w += a0 * v0.w;
                }
            }
        } else {
            float adq[3], mxq[3], invq[3];
#pragma unroll
            for (int t = 0; t < 3; t++) {
                adq[t] = __ldg(cad + nq * 8 + head_t[t]);
                mxq[t] = smx[q][head_t[t]];
                invq[t] = sinv[q][head_t[t]];
            }
            for (int le = 0; le < dq; le++) {
                int s0 = d_csrsrc[bq + le];
                const float4* g0 = (const float4*)(d_g + (size_t)s0 * HIDD);
#pragma unroll
                for (int t = 0; t < 3; t++) {
                    float e = __ldg(cas + s0 * 8 + head_t[t]) + adq[t];
                    e = e > 0.f ? e : 0.2f * e;
                    float a0 = __expf(e - mxq[t]) * invq[t];
                    float4 v0 = g0[j4_t[t]];
                    acc4[t].x += a0 * v0.x;
                    acc4[t].y += a0 * v0.y;
                    acc4[t].z += a0 * v0.z;
                    acc4[t].w += a0 * v0.w;
                }
            }
        }

#pragma unroll
        for (int t = 0; t < 3; t++) {
            int j = 4 * j4_t[t];
            float4 b4 = *(const float4*)(bias + j);
            float4 v = acc4[t];
            v.x = fmaxf(v.x + b4.x, 0.f);
            v.y = fmaxf(v.y + b4.y, 0.f);
            v.z = fmaxf(v.z + b4.z, 0.f);
            v.w = fmaxf(v.w + b4.w, 0.f);
            if (write_h) *(float4*)&d_h[(size_t)nq * HIDD + j] = v;
            write_split4(nq, j, v);
        }
    }
}

// ---------------- pooling / fc ----------------
__global__ void k_pool() {
    int b = blockIdx.x;
    int j = blockIdx.y * 256 + threadIdx.x;
    int beg = d_gstart[b], end = d_gstart[b + 1];
    float s = 0.f;
    for (int n = beg; n < end; n++) s += d_h[(size_t)n * HIDD + j];
    float cnt = (float)(end - beg);
    d_pool[b * HIDD + j] = s / fmaxf(cnt, 1.0f);
}

__global__ void k_fc(const float* __restrict__ W, const float* __restrict__ b,
                     float* __restrict__ out) {
    int id = blockIdx.x * 256 + threadIdx.x;
    if (id >= NGB * EMB) return;
    int bb = id / EMB, k = id % EMB;
    float s = b[k];
    for (int j = 0; j < HIDD; j++) s += d_pool[bb * HIDD + j] * W[j * EMB + k];
    out[id] = s;
}

// ---------------- host launch ----------------
extern "C" void kernel_launch(void* const* d_in, const int* in_sizes, int n_in,
                              void* d_out, int out_size) {
    const float* x     = (const float*)d_in[0];
    const int*   ei    = (const int*)d_in[1];
    const int*   batch = (const int*)d_in[2];
    const float* projW = (const float*)d_in[3];
    const float* projb = (const float*)d_in[4];
    const float* convW = (const float*)d_in[5];
    const float* attS  = (const float*)d_in[6];
    const float* attD  = (const float*)d_in[7];
    const float* convb = (const float*)d_in[8];
    const float* fcW   = (const float*)d_in[9];
    const float* fcb   = (const float*)d_in[10];
    float* out = (float*)d_out;

    static bool attr_set = false;
    if (!attr_set) {
        cudaFuncSetAttribute(k_gemm_hmma, cudaFuncAttributeMaxDynamicSharedMemorySize, SMEM_GEMM);
        attr_set = true;
    }

    void* pW = nullptr;
    cudaGetSymbolAddress(&pW, d_WcatT);
    const __nv_bfloat16* Wcat = (const __nv_bfloat16*)pW;
    void *pa0, *pd0, *pa1, *pd1;
    cudaGetSymbolAddress(&pa0, d_as0);
    cudaGetSymbolAddress(&pd0, d_ad0);
    cudaGetSymbolAddress(&pa1, d_as1);
    cudaGetSymbolAddress(&pd1, d_ad1);
    float* asb[2] = {(float*)pa0, (float*)pa1};
    float* adb[2] = {(float*)pd0, (float*)pd1};

    k_zero_deg<<<(NN + 255) / 256, 256>>>();
    k_hist<<<(EA + 255) / 256, 256>>>(ei);
    k_scan<<<1, 1024>>>();
    k_scatter<<<(EA + 255) / 256, 256>>>(ei);
    k_gstart<<<(NN + 255) / 256, 256>>>(batch);
    k_proj<<<(NN * HIDD + 255) / 256, 256>>>(x, projW, projb);
    k_split_w<<<(NL * HIDD * HIDD + 255) / 256, 256>>>(convW);
    k_zero_asd0<<<(NN * NH + 255) / 256, 256>>>();

    for (int l = 0; l < NL; l++) {
        int cur = l & 1, nxt = cur ^ 1;
        dim3 gg(HIDD / 128, (NN + 127) / 128);   // 6 x 157 = 942 CTAs
        k_gemm_hmma<<<gg, 128, SMEM_GEMM>>>(Wcat + (size_t)l * HIDD * KCAT,
                                            attS + l * HIDD, attD + l * HIDD,
                                            asb[cur], adb[cur]);
        k_attn<<<NN / 8, 256>>>(asb[cur], adb[cur], asb[nxt], adb[nxt],
                                convb + l * HIDD, (l == NL - 1) ? 1 : 0);
    }

    dim3 gp(NGB, 3);
    k_pool<<<gp, 256>>>();
    k_fc<<<(NGB * EMB + 255) / 256, 256>>>(fcW, fcb, out);
}

// round 14
// speedup vs baseline: 1.1709x; 1.0102x over previous
#include <cuda_runtime.h>
#include <cuda_bf16.h>
#include <cstdint>

#define NN 20000
#define EE 320000
#define EA 340000      // E + N self loops
#define HIDD 768
#define NH 8
#define NC 96
#define NL 16
#define NGB 16
#define EMB 512
#define KCAT 2304      // 3 * HIDD (bf16 split: hi*hi + lo*hi + hi*lo)
#define MAXD 64        // smem softmax cache cap (recompute path beyond)
#define NB 1024        // degree histogram bins

// ---------------- scratch (device globals; no allocations) ----------------
__device__ float d_h[NN * HIDD];
__device__ float d_g[NN * HIDD];
__device__ float d_as0[NN * NH];
__device__ float d_ad0[NN * NH];
__device__ float d_as1[NN * NH];
__device__ float d_ad1[NN * NH];
__device__ int   d_deg[NN];
__device__ int   d_rowptr[NN + 1];
__device__ int   d_cursor[NN];
__device__ int   d_csrsrc[EA];
__device__ int   d_gstart[NGB + 1];
__device__ float d_pool[NGB * HIDD];
__device__ int   d_dhist[NB];
__device__ int   d_dcur[NB];
__device__ int   d_perm[NN];
__device__ __nv_bfloat16 d_Acat[(size_t)NN * KCAT];           // h split, [N, 2304]
__device__ __nv_bfloat16 d_WcatT[(size_t)NL * HIDD * KCAT];   // W^T split, [L, 768n, 2304k]

// ---------------- CSR build ----------------
__global__ void k_zero_deg() {
    int i = blockIdx.x * 256 + threadIdx.x;
    if (i < NN) d_deg[i] = 0;
    if (i < NB) d_dhist[i] = 0;
}

__global__ void k_hist(const int* __restrict__ ei) {
    int i = blockIdx.x * 256 + threadIdx.x;
    if (i >= EA) return;
    int dst = (i < EE) ? ei[EE + i] : (i - EE);
    atomicAdd(&d_deg[dst], 1);
}

__global__ void k_scan() {
    __shared__ int sdata[1024];
    __shared__ int carry;
    int tid = threadIdx.x;
    if (tid == 0) { carry = 0; d_rowptr[0] = 0; }
    __syncthreads();
    for (int base = 0; base < NN; base += 1024) {
        int i = base + tid;
        int v = (i < NN) ? d_deg[i] : 0;
        sdata[tid] = v;
        __syncthreads();
        for (int off = 1; off < 1024; off <<= 1) {
            int t = (tid >= off) ? sdata[tid - off] : 0;
            __syncthreads();
            sdata[tid] += t;
            __syncthreads();
        }
        int incl = sdata[tid] + carry;
        if (i < NN) d_rowptr[i + 1] = incl;
        __syncthreads();
        if (tid == 1023) carry = incl;
        __syncthreads();
    }
    for (int i = tid; i < NN; i += 1024) d_cursor[i] = d_rowptr[i];
}

__global__ void k_scatter(const int* __restrict__ ei) {
    int i = blockIdx.x * 256 + threadIdx.x;
    if (i >= EA) return;
    int src, dst;
    if (i < EE) { src = ei[i]; dst = ei[EE + i]; }
    else        { src = i - EE; dst = src; }
    int slot = atomicAdd(&d_cursor[dst], 1);
    d_csrsrc[slot] = src;
}

// ---------------- degree sort (descending) for attn load balance ----------
__global__ void k_dhist() {
    int n = blockIdx.x * 256 + threadIdx.x;
    if (n >= NN) return;
    int d = d_deg[n];
    if (d > NB - 1) d = NB - 1;
    atomicAdd(&d_dhist[d], 1);
}

__global__ void k_dscan() {   // d_dcur[d] = count of nodes with degree > d
    __shared__ int sdata[NB];
    int tid = threadIdx.x;
    sdata[tid] = d_dhist[NB - 1 - tid];  // reversed
    __syncthreads();
    for (int off = 1; off < NB; off <<= 1) {
        int t = (tid >= off) ? sdata[tid - off] : 0;
        __syncthreads();
        sdata[tid] += t;
        __syncthreads();
    }
    // exclusive sum in reversed order = suffix sum beyond d
    int incl = sdata[tid];
    int own = d_dhist[NB - 1 - tid];
    d_dcur[NB - 1 - tid] = incl - own;
    __syncthreads();
}

__global__ void k_dscatter() {
    int n = blockIdx.x * 256 + threadIdx.x;
    if (n >= NN) return;
    int d = d_deg[n];
    if (d > NB - 1) d = NB - 1;
    int slot = atomicAdd(&d_dcur[d], 1);
    d_perm[slot] = n;
}

__global__ void k_gstart(const int* __restrict__ batch) {
    int n = blockIdx.x * 256 + threadIdx.x;
    if (n >= NN) return;
    int b = batch[n];
    if (n == 0) {
        for (int bb = 0; bb <= b; bb++) d_gstart[bb] = 0;
    } else {
        int pb = batch[n - 1];
        if (pb != b) for (int bb = pb + 1; bb <= b; bb++) d_gstart[bb] = n;
    }
    if (n == NN - 1) {
        for (int bb = b + 1; bb <= NGB; bb++) d_gstart[bb] = NN;
    }
}

__global__ void k_zero_asd0() {
    int i = blockIdx.x * 256 + threadIdx.x;
    if (i < NN * NH) { d_as0[i] = 0.f; d_ad0[i] = 0.f; }
}

// ---------------- split write helpers ----------------
__device__ __forceinline__ void write_split(int n, int k, float v) {
    __nv_bfloat16 hi = __float2bfloat16(v);
    __nv_bfloat16 lo = __float2bfloat16(v - __bfloat162float(hi));
    size_t base = (size_t)n * KCAT;
    d_Acat[base + k]            = hi;
    d_Acat[base + HIDD + k]     = lo;
    d_Acat[base + 2 * HIDD + k] = hi;
}

__device__ __forceinline__ void write_split4(int n, int j, float4 v) {
    float vv[4] = {v.x, v.y, v.z, v.w};
    __nv_bfloat162 hp[2], lp[2];
#pragma unroll
    for (int q = 0; q < 2; q++) {
        __nv_bfloat16 h0 = __float2bfloat16(vv[2 * q]);
        __nv_bfloat16 h1 = __float2bfloat16(vv[2 * q + 1]);
        __nv_bfloat16 l0 = __float2bfloat16(vv[2 * q]     - __bfloat162float(h0));
        __nv_bfloat16 l1 = __float2bfloat16(vv[2 * q + 1] - __bfloat162float(h1));
        hp[q] = __nv_bfloat162(h0, h1);
        lp[q] = __nv_bfloat162(l0, l1);
    }
    size_t base = (size_t)n * KCAT;
    __nv_bfloat162* p0 = (__nv_bfloat162*)&d_Acat[base + j];
    __nv_bfloat162* p1 = (__nv_bfloat162*)&d_Acat[base + HIDD + j];
    __nv_bfloat162* p2 = (__nv_bfloat162*)&d_Acat[base + 2 * HIDD + j];
    p0[0] = hp[0]; p0[1] = hp[1];
    p1[0] = lp[0]; p1[1] = lp[1];
    p2[0] = hp[0]; p2[1] = hp[1];
}

// ---------------- input projection (split only) ----------------
__global__ void k_proj(const float* __restrict__ x, const float* __restrict__ W,
                       const float* __restrict__ b) {
    int id = blockIdx.x * 256 + threadIdx.x;
    if (id >= NN * HIDD) return;
    int n = id / HIDD, j = id % HIDD;
    float s = b[j];
#pragma unroll
    for (int f = 0; f < 5; f++) s += x[n * 5 + f] * W[f * HIDD + j];
    write_split(n, j, s);
}

// ---------------- bf16 split: weights (once) ----------------
__global__ void k_split_w(const float* __restrict__ convW) {
    int id = blockIdx.x * 256 + threadIdx.x;
    if (id >= NL * HIDD * HIDD) return;
    int l = id / (HIDD * HIDD);
    int rem = id % (HIDD * HIDD);
    int k = rem / HIDD, n = rem % HIDD;
    float v = convW[id];
    __nv_bfloat16 hi = __float2bfloat16(v);
    __nv_bfloat16 lo = __float2bfloat16(v - __bfloat162float(hi));
    size_t base = ((size_t)l * HIDD + n) * KCAT;
    d_WcatT[base + k]            = hi;
    d_WcatT[base + HIDD + k]     = hi;
    d_WcatT[base + 2 * HIDD + k] = lo;
}

// =====================================================================
// HMMA GEMM: 128x128 CTA tile, 128 threads (2m x 2n warps of 64x64),
// BK=64, 3-stage cp.async, 2 CTAs/SM. Fused asd epilogue.
// =====================================================================
#define BK 64
#define STAGES 3
#define STG_A 16384
#define STG_B 16384
#define SMEM_GEMM (STAGES * (STG_A + STG_B))   // 98304

__device__ __forceinline__ uint32_t swz(uint32_t b) { return b ^ ((b >> 3) & 0x70); }

__device__ __forceinline__ uint32_t smem_u32(const void* p) {
    uint32_t a;
    asm("{ .reg .u64 t; cvta.to.shared.u64 t, %1; cvt.u32.u64 %0, t; }" : "=r"(a) : "l"(p));
    return a;
}

#define CP_ASYNC(dst, src, sz) \
    asm volatile("cp.async.cg.shared.global [%0], [%1], 16, %2;" \
        :: "r"(dst), "l"(src), "r"(sz))
#define CP_COMMIT() asm volatile("cp.async.commit_group;")
#define CP_WAIT1()  asm volatile("cp.async.wait_group 1;")

#define LDMX4(r0, r1, r2, r3, a) \
    asm volatile("ldmatrix.sync.aligned.m8n8.x4.shared.b16 {%0,%1,%2,%3}, [%4];" \
        : "=r"(r0), "=r"(r1), "=r"(r2), "=r"(r3) : "r"(a))

#define MMA16816(d, a, b) \
    asm volatile("mma.sync.aligned.m16n8k16.row.col.f32.bf16.bf16.f32 " \
        "{%0,%1,%2,%3}, {%4,%5,%6,%7}, {%8,%9}, {%0,%1,%2,%3};" \
        : "+f"((d)[0]), "+f"((d)[1]), "+f"((d)[2]), "+f"((d)[3]) \
        : "r"((a)[0]), "r"((a)[1]), "r"((a)[2]), "r"((a)[3]), "r"((b)[0]), "r"((b)[1]))

__global__ __launch_bounds__(128, 2) void k_gemm_hmma(
    const __nv_bfloat16* __restrict__ Wl,
    const float* __restrict__ attS, const float* __restrict__ attD,
    float* __restrict__ asb, float* __restrict__ adb)
{
    extern __shared__ __align__(128) char smem[];
    uint32_t sA = smem_u32(smem);
    uint32_t sB = sA + STAGES * STG_A;

    const int tid = threadIdx.x;
    const int lane = tid & 31, warp = tid >> 5;
    const int wm = warp & 1, wn = warp >> 1;
    const int mtile = blockIdx.y, ntile = blockIdx.x;
    const int mbase = mtile * 128;
    const int nbase = ntile * 128;

    const __nv_bfloat16* Ag = d_Acat;

    auto issue_stage = [&](int kt, int st) {
        int k0 = kt * BK;
        uint32_t a_dst = sA + st * STG_A;
#pragma unroll
        for (int it = 0; it < 8; it++) {
            int id = it * 128 + tid;
            int row = id >> 3, ck = id & 7;
            int gr = mbase + row;
            const __nv_bfloat16* srcA = Ag + (size_t)gr * KCAT + k0 + ck * 8;
            CP_ASYNC(a_dst + swz(row * 128 + ck * 16), srcA, (gr < NN) ? 16 : 0);
        }
        uint32_t b_dst = sB + st * STG_B;
#pragma unroll
        for (int it = 0; it < 8; it++) {
            int id = it * 128 + tid;
            int row = id >> 3, ck = id & 7;
            const __nv_bfloat16* srcB = Wl + (size_t)(nbase + row) * KCAT + k0 + ck * 8;
            CP_ASYNC(b_dst + swz(row * 128 + ck * 16), srcB, 16);
        }
        CP_COMMIT();
    };

    issue_stage(0, 0);
    issue_stage(1, 1);

    float acc[4][8][4];
#pragma unroll
    for (int i = 0; i < 4; i++)
#pragma unroll
        for (int j = 0; j < 8; j++)
#pragma unroll
            for (int c = 0; c < 4; c++) acc[i][j][c] = 0.f;

    const int NKT = KCAT / BK;
    for (int kt = 0; kt < NKT; kt++) {
        CP_WAIT1();
        __syncthreads();
        if (kt + 2 < NKT) issue_stage(kt + 2, (kt + 2) % STAGES);
        else CP_COMMIT();

        int st = kt % STAGES;
        uint32_t aS = sA + st * STG_A;
        uint32_t bS = sB + st * STG_B;

#pragma unroll
        for (int ks = 0; ks < 4; ks++) {
            uint32_t afr[4][4];
#pragma unroll
            for (int im = 0; im < 4; im++) {
                int row = wm * 64 + im * 16 + (lane & 15);
                int kk = ks * 16 + (lane >> 4) * 8;
                LDMX4(afr[im][0], afr[im][1], afr[im][2], afr[im][3],
                      aS + swz(row * 128 + kk * 2));
            }
            uint32_t bfr[8][2];
#pragma unroll
            for (int pr = 0; pr < 4; pr++) {
                int nrow = wn * 64 + pr * 16 + (lane & 7) + ((lane & 16) ? 8 : 0);
                int kk = ks * 16 + ((lane & 8) ? 8 : 0);
                uint32_t r0, r1, r2, r3;
                LDMX4(r0, r1, r2, r3, bS + swz(nrow * 128 + kk * 2));
                bfr[pr * 2][0] = r0;     bfr[pr * 2][1] = r1;
                bfr[pr * 2 + 1][0] = r2; bfr[pr * 2 + 1][1] = r3;
            }
#pragma unroll
            for (int im = 0; im < 4; im++)
#pragma unroll
                for (int jn = 0; jn < 8; jn++)
                    MMA16816(acc[im][jn], afr[im], bfr[jn]);
        }
    }

    // ---------------- fused epilogue ----------------
    const int base0 = nbase + wn * 64;
    const int hA = base0 / 96;
    float ps[4][2][2];
    float pd[4][2][2];
#pragma unroll
    for (int a = 0; a < 4; a++)
#pragma unroll
        for (int b = 0; b < 2; b++)
#pragma unroll
            for (int c = 0; c < 2; c++) { ps[a][b][c] = 0.f; pd[a][b][c] = 0.f; }

#pragma unroll
    for (int jn = 0; jn < 8; jn++) {
        int col = base0 + jn * 8 + (lane & 3) * 2;
        int slot = (col / 96) - hA;
        float as0 = __ldg(attS + col), as1 = __ldg(attS + col + 1);
        float ad0 = __ldg(attD + col), ad1 = __ldg(attD + col + 1);
#pragma unroll
        for (int im = 0; im < 4; im++) {
            int r0 = mbase + wm * 64 + im * 16 + (lane >> 2);
            if (r0 < NN)
                *(float2*)&d_g[(size_t)r0 * HIDD + col] =
                    make_float2(acc[im][jn][0], acc[im][jn][1]);
            if (r0 + 8 < NN)
                *(float2*)&d_g[(size_t)(r0 + 8) * HIDD + col] =
                    make_float2(acc[im][jn][2], acc[im][jn][3]);
            ps[im][0][slot] += acc[im][jn][0] * as0 + acc[im][jn][1] * as1;
            pd[im][0][slot] += acc[im][jn][0] * ad0 + acc[im][jn][1] * ad1;
            ps[im][1][slot] += acc[im][jn][2] * as0 + acc[im][jn][3] * as1;
            pd[im][1][slot] += acc[im][jn][2] * ad0 + acc[im][jn][3] * ad1;
        }
    }
#pragma unroll
    for (int im = 0; im < 4; im++)
#pragma unroll
        for (int rh = 0; rh < 2; rh++)
#pragma unroll
            for (int sl = 0; sl < 2; sl++) {
                float vs = ps[im][rh][sl], vd = pd[im][rh][sl];
                vs += __shfl_xor_sync(0xffffffffu, vs, 1);
                vs += __shfl_xor_sync(0xffffffffu, vs, 2);
                vd += __shfl_xor_sync(0xffffffffu, vd, 1);
                vd += __shfl_xor_sync(0xffffffffu, vd, 2);
                if ((lane & 3) == 0) {
                    int row = mbase + wm * 64 + im * 16 + (lane >> 2) + rh * 8;
                    int h = hA + sl;
                    if (row < NN && h < NH) {
                        atomicAdd(&asb[row * 8 + h], vs);
                        atomicAdd(&adb[row * 8 + h], vd);
                    }
                }
            }
}

// =====================================================================
// Attention: degree-sorted nodes (LPT), per-warp softmax + pair-balanced
// channel-split gather. block = 256 = 8 nodes via d_perm.
// =====================================================================
__global__ __launch_bounds__(256) void k_attn(
    const float* __restrict__ cas, const float* __restrict__ cad,
    float* __restrict__ nas, float* __restrict__ nad,
    const float* __restrict__ bias, int write_h)
{
    __shared__ float ebuf[8][MAXD * 8];   // 16 KB alpha cache
    __shared__ float smx[8][8];
    __shared__ float sinv[8][8];
    __shared__ int   snode[8];

    const int warp = threadIdx.x >> 5, lane = threadIdx.x & 31;
    const int blkbase = blockIdx.x * 8;
    const int n = d_perm[blkbase + warp];
    if (lane == 0) snode[warp] = n;

    if (lane < 8) { nas[n * 8 + lane] = 0.f; nad[n * 8 + lane] = 0.f; }

    const int beg = d_rowptr[n], end = d_rowptr[n + 1];
    const int deg = end - beg;

    const float4* adp = (const float4*)(cad + n * 8);
    float4 ad0 = adp[0], ad1 = adp[1];
    float ad[8] = {ad0.x, ad0.y, ad0.z, ad0.w, ad1.x, ad1.y, ad1.z, ad1.w};

    // ---------- phase 1: per-warp softmax for own node ----------
    float mx[8];
#pragma unroll
    for (int h = 0; h < 8; h++) mx[h] = -1e30f;
    if (deg <= MAXD) {
#pragma unroll
        for (int it = 0; it < 2; it++) {
            int le = it * 32 + lane;
            if (le < deg) {
                int s = d_csrsrc[beg + le];
                const float4* ap = (const float4*)(cas + s * 8);
                float4 a0 = ap[0], a1 = ap[1];
                float ev[8] = {a0.x, a0.y, a0.z, a0.w, a1.x, a1.y, a1.z, a1.w};
#pragma unroll
                for (int h = 0; h < 8; h++) {
                    float e = ev[h] + ad[h];
                    e = e > 0.f ? e : 0.2f * e;
                    ebuf[warp][le * 8 + h] = e;
                    mx[h] = fmaxf(mx[h], e);
                }
            }
        }
    } else {
        for (int i0 = beg + lane; i0 < end; i0 += 32) {
            int s = d_csrsrc[i0];
            const float4* ap = (const float4*)(cas + s * 8);
            float4 a0 = ap[0], a1 = ap[1];
            float ev[8] = {a0.x, a0.y, a0.z, a0.w, a1.x, a1.y, a1.z, a1.w};
#pragma unroll
            for (int h = 0; h < 8; h++) {
                float e = ev[h] + ad[h];
                e = e > 0.f ? e : 0.2f * e;
                mx[h] = fmaxf(mx[h], e);
            }
        }
    }
#pragma unroll
    for (int h = 0; h < 8; h++)
        for (int off = 16; off; off >>= 1)
            mx[h] = fmaxf(mx[h], __shfl_xor_sync(0xffffffffu, mx[h], off));
    __syncwarp();

    float sm[8];
#pragma unroll
    for (int h = 0; h < 8; h++) sm[h] = 0.f;
    if (deg <= MAXD) {
#pragma unroll
        for (int it = 0; it < 2; it++) {
            int le = it * 32 + lane;
            if (le < deg) {
#pragma unroll
                for (int h = 0; h < 8; h++) {
                    float p = __expf(ebuf[warp][le * 8 + h] - mx[h]);
                    ebuf[warp][le * 8 + h] = p;
                    sm[h] += p;
                }
            }
        }
    } else {
        for (int i0 = beg + lane; i0 < end; i0 += 32) {
            int s = d_csrsrc[i0];
            const float4* ap = (const float4*)(cas + s * 8);
            float4 a0 = ap[0], a1 = ap[1];
            float ev[8] = {a0.x, a0.y, a0.z, a0.w, a1.x, a1.y, a1.z, a1.w};
#pragma unroll
            for (int h = 0; h < 8; h++) {
                float e = ev[h] + ad[h];
                e = e > 0.f ? e : 0.2f * e;
                sm[h] += __expf(e - mx[h]);
            }
        }
    }
#pragma unroll
    for (int h = 0; h < 8; h++)
        for (int off = 16; off; off >>= 1)
            sm[h] += __shfl_xor_sync(0xffffffffu, sm[h], off);
    float inv[8];
#pragma unroll
    for (int h = 0; h < 8; h++) inv[h] = 1.f / (sm[h] + 1e-16f);
    if (lane < 8) { smx[warp][lane] = mx[lane]; sinv[warp][lane] = inv[lane]; }
    __syncwarp();

    if (deg <= MAXD) {
#pragma unroll
        for (int it = 0; it < 2; it++) {
            int le = it * 32 + lane;
            if (le < deg) {
#pragma unroll
                for (int h = 0; h < 8; h++)
                    ebuf[warp][le * 8 + h] *= inv[h];
            }
        }
    }
    __syncthreads();

    // ---------- phase 2: pair-balanced gather ----------
    const int pw = warp & 1;
    const int q0 = warp & ~1;
    int slot_t[3], head_t[3], j4_t[3];
#pragma unroll
    for (int t = 0; t < 3; t++) {
        slot_t[t] = pw * 3 + t;
        j4_t[t] = lane + 32 * slot_t[t];
        head_t[t] = j4_t[t] / 24;
    }

#pragma unroll
    for (int qi = 0; qi < 2; qi++) {
        int q = q0 + qi;
        int nq = snode[q];
        int bq = d_rowptr[nq], eq = d_rowptr[nq + 1];
        int dq = eq - bq;

        float4 acc4[3];
#pragma unroll
        for (int t = 0; t < 3; t++) acc4[t] = make_float4(0.f, 0.f, 0.f, 0.f);

        if (dq <= MAXD) {
            int le = 0;
            for (; le + 4 <= dq; le += 4) {
                int s0 = d_csrsrc[bq + le];
                int s1 = d_csrsrc[bq + le + 1];
                int s2 = d_csrsrc[bq + le + 2];
                int s3 = d_csrsrc[bq + le + 3];
                const float4* g0 = (const float4*)(d_g + (size_t)s0 * HIDD);
                const float4* g1 = (const float4*)(d_g + (size_t)s1 * HIDD);
                const float4* g2 = (const float4*)(d_g + (size_t)s2 * HIDD);
                const float4* g3 = (const float4*)(d_g + (size_t)s3 * HIDD);
#pragma unroll
                for (int t = 0; t < 3; t++) {
                    int j4 = j4_t[t], hh = head_t[t];
                    float a0 = ebuf[q][le * 8 + hh];
                    float a1 = ebuf[q][(le + 1) * 8 + hh];
                    float a2 = ebuf[q][(le + 2) * 8 + hh];
                    float a3 = ebuf[q][(le + 3) * 8 + hh];
                    float4 v0 = g0[j4], v1 = g1[j4], v2 = g2[j4], v3 = g3[j4];
                    acc4[t].x += a0 * v0.x + a1 * v1.x + a2 * v2.x + a3 * v3.x;
                    acc4[t].y += a0 * v0.y + a1 * v1.y + a2 * v2.y + a3 * v3.y;
                    acc4[t].z += a0 * v0.z + a1 * v1.z + a2 * v2.z + a3 * v3.z;
                    acc4[t].w += a0 * v0.w + a1 * v1.w + a2 * v2.w + a3 * v3.w;
                }
            }
            for (; le < dq; le++) {
                int s0 = d_csrsrc[bq + le];
                const float4* g0 = (const float4*)(d_g + (size_t)s0 * HIDD);
#pragma unroll
                for (int t = 0; t < 3; t++) {
                    float a0 = ebuf[q][le * 8 + head_t[t]];
                    float4 v0 = g0[j4_t[t]];
                    acc4[t].x += a0 * v0.x;
                    acc4[t].y += a0 * v0.y;
                    acc4[t].z += a0 * v0.z;
                    acc4[t].w += a0 * v0.w;
                }
            }
        } else {
            float adq[3], mxq[3], invq[3];
#pragma unroll
            for (int t = 0; t < 3; t++) {
                adq[t] = __ldg(cad + nq * 8 + head_t[t]);
                mxq[t] = smx[q][head_t[t]];
                invq[t] = sinv[q][head_t[t]];
            }
            for (int le = 0; le < dq; le++) {
                int s0 = d_csrsrc[bq + le];
                const float4* g0 = (const float4*)(d_g + (size_t)s0 * HIDD);
#pragma unroll
                for (int t = 0; t < 3; t++) {
                    float e = __ldg(cas + s0 * 8 + head_t[t]) + adq[t];
                    e = e > 0.f ? e : 0.2f * e;
                    float a0 = __expf(e - mxq[t]) * invq[t];
                    float4 v0 = g0[j4_t[t]];
                    acc4[t].x += a0 * v0.x;
                    acc4[t].y += a0 * v0.y;
                    acc4[t].z += a0 * v0.z;
                    acc4[t].w += a0 * v0.w;
                }
            }
        }

#pragma unroll
        for (int t = 0; t < 3; t++) {
            int j = 4 * j4_t[t];
            float4 b4 = *(const float4*)(bias + j);
            float4 v = acc4[t];
            v.x = fmaxf(v.x + b4.x, 0.f);
            v.y = fmaxf(v.y + b4.y, 0.f);
            v.z = fmaxf(v.z + b4.z, 0.f);
            v.w = fmaxf(v.w + b4.w, 0.f);
            if (write_h) *(float4*)&d_h[(size_t)nq * HIDD + j] = v;
            write_split4(nq, j, v);
        }
    }
}

// ---------------- pooling / fc ----------------
__global__ void k_pool() {
    int b = blockIdx.x;
    int j = blockIdx.y * 256 + threadIdx.x;
    int beg = d_gstart[b], end = d_gstart[b + 1];
    float s = 0.f;
    for (int n = beg; n < end; n++) s += d_h[(size_t)n * HIDD + j];
    float cnt = (float)(end - beg);
    d_pool[b * HIDD + j] = s / fmaxf(cnt, 1.0f);
}

__global__ void k_fc(const float* __restrict__ W, const float* __restrict__ b,
                     float* __restrict__ out) {
    int id = blockIdx.x * 256 + threadIdx.x;
    if (id >= NGB * EMB) return;
    int bb = id / EMB, k = id % EMB;
    float s = b[k];
    for (int j = 0; j < HIDD; j++) s += d_pool[bb * HIDD + j] * W[j * EMB + k];
    out[id] = s;
}

// ---------------- host launch ----------------
extern "C" void kernel_launch(void* const* d_in, const int* in_sizes, int n_in,
                              void* d_out, int out_size) {
    const float* x     = (const float*)d_in[0];
    const int*   ei    = (const int*)d_in[1];
    const int*   batch = (const int*)d_in[2];
    const float* projW = (const float*)d_in[3];
    const float* projb = (const float*)d_in[4];
    const float* convW = (const float*)d_in[5];
    const float* attS  = (const float*)d_in[6];
    const float* attD  = (const float*)d_in[7];
    const float* convb = (const float*)d_in[8];
    const float* fcW   = (const float*)d_in[9];
    const float* fcb   = (const float*)d_in[10];
    float* out = (float*)d_out;

    static bool attr_set = false;
    if (!attr_set) {
        cudaFuncSetAttribute(k_gemm_hmma, cudaFuncAttributeMaxDynamicSharedMemorySize, SMEM_GEMM);
        attr_set = true;
    }

    void* pW = nullptr;
    cudaGetSymbolAddress(&pW, d_WcatT);
    const __nv_bfloat16* Wcat = (const __nv_bfloat16*)pW;
    void *pa0, *pd0, *pa1, *pd1;
    cudaGetSymbolAddress(&pa0, d_as0);
    cudaGetSymbolAddress(&pd0, d_ad0);
    cudaGetSymbolAddress(&pa1, d_as1);
    cudaGetSymbolAddress(&pd1, d_ad1);
    float* asb[2] = {(float*)pa0, (float*)pa1};
    float* adb[2] = {(float*)pd0, (float*)pd1};

    k_zero_deg<<<(NN + 255) / 256, 256>>>();
    k_hist<<<(EA + 255) / 256, 256>>>(ei);
    k_scan<<<1, 1024>>>();
    k_scatter<<<(EA + 255) / 256, 256>>>(ei);
    k_dhist<<<(NN + 255) / 256, 256>>>();
    k_dscan<<<1, NB>>>();
    k_dscatter<<<(NN + 255) / 256, 256>>>();
    k_gstart<<<(NN + 255) / 256, 256>>>(batch);
    k_proj<<<(NN * HIDD + 255) / 256, 256>>>(x, projW, projb);
    k_split_w<<<(NL * HIDD * HIDD + 255) / 256, 256>>>(convW);
    k_zero_asd0<<<(NN * NH + 255) / 256, 256>>>();

    for (int l = 0; l < NL; l++) {
        int cur = l & 1, nxt = cur ^ 1;
        dim3 gg(HIDD / 128, (NN + 127) / 128);   // 6 x 157 = 942 CTAs
        k_gemm_hmma<<<gg, 128, SMEM_GEMM>>>(Wcat + (size_t)l * HIDD * KCAT,
                                            attS + l * HIDD, attD + l * HIDD,
                                            asb[cur], adb[cur]);
        k_attn<<<NN / 8, 256>>>(asb[cur], adb[cur], asb[nxt], adb[nxt],
                                convb + l * HIDD, (l == NL - 1) ? 1 : 0);
    }

    dim3 gp(NGB, 3);
    k_pool<<<gp, 256>>>();
    k_fc<<<(NGB * EMB + 255) / 256, 256>>>(fcW, fcb, out);
}

// round 15
// speedup vs baseline: 1.2213x; 1.0430x over previous
#include <cuda_runtime.h>
#include <cuda_bf16.h>
#include <cstdint>

#define NN 20000
#define EE 320000
#define EA 340000      // E + N self loops
#define HIDD 768
#define NH 8
#define NC 96
#define NL 16
#define NGB 16
#define EMB 512
#define KCAT 2304      // logical K: hi*Whi + lo*Whi + hi*Wlo
#define ACAT 1536      // physical A columns (hi, lo); third segment remaps to first
#define MAXD 64        // smem softmax cache cap (recompute path beyond)
#define NB 1024        // degree histogram bins

// ---------------- scratch (device globals; no allocations) ----------------
__device__ float d_h[NN * HIDD];
__device__ float d_g[NN * HIDD];
__device__ float d_as0[NN * NH];
__device__ float d_ad0[NN * NH];
__device__ float d_as1[NN * NH];
__device__ float d_ad1[NN * NH];
__device__ int   d_deg[NN];
__device__ int   d_rowptr[NN + 1];
__device__ int   d_cursor[NN];
__device__ int   d_csrsrc[EA];
__device__ int   d_gstart[NGB + 1];
__device__ float d_pool[NGB * HIDD];
__device__ int   d_dhist[NB];
__device__ int   d_dcur[NB];
__device__ int   d_perm[NN];
__device__ __nv_bfloat16 d_Acat[(size_t)NN * ACAT];           // h split, [N, 1536]
__device__ __nv_bfloat16 d_WcatT[(size_t)NL * HIDD * KCAT];   // W^T split, [L, 768n, 2304k]

// ---------------- CSR build ----------------
__global__ void k_zero_deg() {
    int i = blockIdx.x * 256 + threadIdx.x;
    if (i < NN) d_deg[i] = 0;
    if (i < NB) d_dhist[i] = 0;
}

__global__ void k_hist(const int* __restrict__ ei) {
    int i = blockIdx.x * 256 + threadIdx.x;
    if (i >= EA) return;
    int dst = (i < EE) ? ei[EE + i] : (i - EE);
    atomicAdd(&d_deg[dst], 1);
}

__global__ void k_scan() {
    __shared__ int sdata[1024];
    __shared__ int carry;
    int tid = threadIdx.x;
    if (tid == 0) { carry = 0; d_rowptr[0] = 0; }
    __syncthreads();
    for (int base = 0; base < NN; base += 1024) {
        int i = base + tid;
        int v = (i < NN) ? d_deg[i] : 0;
        sdata[tid] = v;
        __syncthreads();
        for (int off = 1; off < 1024; off <<= 1) {
            int t = (tid >= off) ? sdata[tid - off] : 0;
            __syncthreads();
            sdata[tid] += t;
            __syncthreads();
        }
        int incl = sdata[tid] + carry;
        if (i < NN) d_rowptr[i + 1] = incl;
        __syncthreads();
        if (tid == 1023) carry = incl;
        __syncthreads();
    }
    for (int i = tid; i < NN; i += 1024) d_cursor[i] = d_rowptr[i];
}

__global__ void k_scatter(const int* __restrict__ ei) {
    int i = blockIdx.x * 256 + threadIdx.x;
    if (i >= EA) return;
    int src, dst;
    if (i < EE) { src = ei[i]; dst = ei[EE + i]; }
    else        { src = i - EE; dst = src; }
    int slot = atomicAdd(&d_cursor[dst], 1);
    d_csrsrc[slot] = src;
}

// ---------------- degree sort (descending) for attn load balance ----------
__global__ void k_dhist() {
    int n = blockIdx.x * 256 + threadIdx.x;
    if (n >= NN) return;
    int d = d_deg[n];
    if (d > NB - 1) d = NB - 1;
    atomicAdd(&d_dhist[d], 1);
}

__global__ void k_dscan() {
    __shared__ int sdata[NB];
    int tid = threadIdx.x;
    sdata[tid] = d_dhist[NB - 1 - tid];
    __syncthreads();
    for (int off = 1; off < NB; off <<= 1) {
        int t = (tid >= off) ? sdata[tid - off] : 0;
        __syncthreads();
        sdata[tid] += t;
        __syncthreads();
    }
    int incl = sdata[tid];
    int own = d_dhist[NB - 1 - tid];
    d_dcur[NB - 1 - tid] = incl - own;
    __syncthreads();
}

__global__ void k_dscatter() {
    int n = blockIdx.x * 256 + threadIdx.x;
    if (n >= NN) return;
    int d = d_deg[n];
    if (d > NB - 1) d = NB - 1;
    int slot = atomicAdd(&d_dcur[d], 1);
    d_perm[slot] = n;
}

__global__ void k_gstart(const int* __restrict__ batch) {
    int n = blockIdx.x * 256 + threadIdx.x;
    if (n >= NN) return;
    int b = batch[n];
    if (n == 0) {
        for (int bb = 0; bb <= b; bb++) d_gstart[bb] = 0;
    } else {
        int pb = batch[n - 1];
        if (pb != b) for (int bb = pb + 1; bb <= b; bb++) d_gstart[bb] = n;
    }
    if (n == NN - 1) {
        for (int bb = b + 1; bb <= NGB; bb++) d_gstart[bb] = NN;
    }
}

__global__ void k_zero_asd0() {
    int i = blockIdx.x * 256 + threadIdx.x;
    if (i < NN * NH) { d_as0[i] = 0.f; d_ad0[i] = 0.f; }
}

// ---------------- split write helpers (2 physical segments) -------------
__device__ __forceinline__ void write_split(int n, int k, float v) {
    __nv_bfloat16 hi = __float2bfloat16(v);
    __nv_bfloat16 lo = __float2bfloat16(v - __bfloat162float(hi));
    size_t base = (size_t)n * ACAT;
    d_Acat[base + k]        = hi;
    d_Acat[base + HIDD + k] = lo;
}

__device__ __forceinline__ void write_split4(int n, int j, float4 v) {
    float vv[4] = {v.x, v.y, v.z, v.w};
    __nv_bfloat162 hp[2], lp[2];
#pragma unroll
    for (int q = 0; q < 2; q++) {
        __nv_bfloat16 h0 = __float2bfloat16(vv[2 * q]);
        __nv_bfloat16 h1 = __float2bfloat16(vv[2 * q + 1]);
        __nv_bfloat16 l0 = __float2bfloat16(vv[2 * q]     - __bfloat162float(h0));
        __nv_bfloat16 l1 = __float2bfloat16(vv[2 * q + 1] - __bfloat162float(h1));
        hp[q] = __nv_bfloat162(h0, h1);
        lp[q] = __nv_bfloat162(l0, l1);
    }
    size_t base = (size_t)n * ACAT;
    __nv_bfloat162* p0 = (__nv_bfloat162*)&d_Acat[base + j];
    __nv_bfloat162* p1 = (__nv_bfloat162*)&d_Acat[base + HIDD + j];
    p0[0] = hp[0]; p0[1] = hp[1];
    p1[0] = lp[0]; p1[1] = lp[1];
}

// ---------------- input projection (split only) ----------------
__global__ void k_proj(const float* __restrict__ x, const float* __restrict__ W,
                       const float* __restrict__ b) {
    int id = blockIdx.x * 256 + threadIdx.x;
    if (id >= NN * HIDD) return;
    int n = id / HIDD, j = id % HIDD;
    float s = b[j];
#pragma unroll
    for (int f = 0; f < 5; f++) s += x[n * 5 + f] * W[f * HIDD + j];
    write_split(n, j, s);
}

// ---------------- bf16 split: weights (once; W keeps 3 segments) --------
__global__ void k_split_w(const float* __restrict__ convW) {
    int id = blockIdx.x * 256 + threadIdx.x;
    if (id >= NL * HIDD * HIDD) return;
    int l = id / (HIDD * HIDD);
    int rem = id % (HIDD * HIDD);
    int k = rem / HIDD, n = rem % HIDD;
    float v = convW[id];
    __nv_bfloat16 hi = __float2bfloat16(v);
    __nv_bfloat16 lo = __float2bfloat16(v - __bfloat162float(hi));
    size_t base = ((size_t)l * HIDD + n) * KCAT;
    d_WcatT[base + k]            = hi;   // pairs A seg0 (hi)
    d_WcatT[base + HIDD + k]     = hi;   // pairs A seg1 (lo)
    d_WcatT[base + 2 * HIDD + k] = lo;   // pairs A seg0 again (hi)
}

// =====================================================================
// HMMA GEMM: 128x128 CTA tile, 128 threads (2m x 2n warps of 64x64),
// BK=64, 3-stage cp.async, 2 CTAs/SM. A K-segment 2 remaps to segment 0.
// =====================================================================
#define BK 64
#define STAGES 3
#define STG_A 16384
#define STG_B 16384
#define SMEM_GEMM (STAGES * (STG_A + STG_B))   // 98304

__device__ __forceinline__ uint32_t swz(uint32_t b) { return b ^ ((b >> 3) & 0x70); }

__device__ __forceinline__ uint32_t smem_u32(const void* p) {
    uint32_t a;
    asm("{ .reg .u64 t; cvta.to.shared.u64 t, %1; cvt.u32.u64 %0, t; }" : "=r"(a) : "l"(p));
    return a;
}

#define CP_ASYNC(dst, src, sz) \
    asm volatile("cp.async.cg.shared.global [%0], [%1], 16, %2;" \
        :: "r"(dst), "l"(src), "r"(sz))
#define CP_COMMIT() asm volatile("cp.async.commit_group;")
#define CP_WAIT1()  asm volatile("cp.async.wait_group 1;")

#define LDMX4(r0, r1, r2, r3, a) \
    asm volatile("ldmatrix.sync.aligned.m8n8.x4.shared.b16 {%0,%1,%2,%3}, [%4];" \
        : "=r"(r0), "=r"(r1), "=r"(r2), "=r"(r3) : "r"(a))

#define MMA16816(d, a, b) \
    asm volatile("mma.sync.aligned.m16n8k16.row.col.f32.bf16.bf16.f32 " \
        "{%0,%1,%2,%3}, {%4,%5,%6,%7}, {%8,%9}, {%0,%1,%2,%3};" \
        : "+f"((d)[0]), "+f"((d)[1]), "+f"((d)[2]), "+f"((d)[3]) \
        : "r"((a)[0]), "r"((a)[1]), "r"((a)[2]), "r"((a)[3]), "r"((b)[0]), "r"((b)[1]))

__global__ __launch_bounds__(128, 2) void k_gemm_hmma(
    const __nv_bfloat16* __restrict__ Wl,
    const float* __restrict__ attS, const float* __restrict__ attD,
    float* __restrict__ asb, float* __restrict__ adb)
{
    extern __shared__ __align__(128) char smem[];
    uint32_t sA = smem_u32(smem);
    uint32_t sB = sA + STAGES * STG_A;

    const int tid = threadIdx.x;
    const int lane = tid & 31, warp = tid >> 5;
    const int wm = warp & 1, wn = warp >> 1;
    const int mtile = blockIdx.y, ntile = blockIdx.x;
    const int mbase = mtile * 128;
    const int nbase = ntile * 128;

    const __nv_bfloat16* Ag = d_Acat;

    auto issue_stage = [&](int kt, int st) {
        // A: logical K segment 2 (kt >= 24) re-reads physical segment 0
        int kA = (kt >= 24) ? (kt - 24) * BK : kt * BK;
        int kB = kt * BK;
        uint32_t a_dst = sA + st * STG_A;
#pragma unroll
        for (int it = 0; it < 8; it++) {
            int id = it * 128 + tid;
            int row = id >> 3, ck = id & 7;
            int gr = mbase + row;
            const __nv_bfloat16* srcA = Ag + (size_t)gr * ACAT + kA + ck * 8;
            CP_ASYNC(a_dst + swz(row * 128 + ck * 16), srcA, (gr < NN) ? 16 : 0);
        }
        uint32_t b_dst = sB + st * STG_B;
#pragma unroll
        for (int it = 0; it < 8; it++) {
            int id = it * 128 + tid;
            int row = id >> 3, ck = id & 7;
            const __nv_bfloat16* srcB = Wl + (size_t)(nbase + row) * KCAT + kB + ck * 8;
            CP_ASYNC(b_dst + swz(row * 128 + ck * 16), srcB, 16);
        }
        CP_COMMIT();
    };

    issue_stage(0, 0);
    issue_stage(1, 1);

    float acc[4][8][4];
#pragma unroll
    for (int i = 0; i < 4; i++)
#pragma unroll
        for (int j = 0; j < 8; j++)
#pragma unroll
            for (int c = 0; c < 4; c++) acc[i][j][c] = 0.f;

    const int NKT = KCAT / BK;   // 36
    for (int kt = 0; kt < NKT; kt++) {
        CP_WAIT1();
        __syncthreads();
        if (kt + 2 < NKT) issue_stage(kt + 2, (kt + 2) % STAGES);
        else CP_COMMIT();

        int st = kt % STAGES;
        uint32_t aS = sA + st * STG_A;
        uint32_t bS = sB + st * STG_B;

#pragma unroll
        for (int ks = 0; ks < 4; ks++) {
            uint32_t afr[4][4];
#pragma unroll
            for (int im = 0; im < 4; im++) {
                int row = wm * 64 + im * 16 + (lane & 15);
                int kk = ks * 16 + (lane >> 4) * 8;
                LDMX4(afr[im][0], afr[im][1], afr[im][2], afr[im][3],
                      aS + swz(row * 128 + kk * 2));
            }
            uint32_t bfr[8][2];
#pragma unroll
            for (int pr = 0; pr < 4; pr++) {
                int nrow = wn * 64 + pr * 16 + (lane & 7) + ((lane & 16) ? 8 : 0);
                int kk = ks * 16 + ((lane & 8) ? 8 : 0);
                uint32_t r0, r1, r2, r3;
                LDMX4(r0, r1, r2, r3, bS + swz(nrow * 128 + kk * 2));
                bfr[pr * 2][0] = r0;     bfr[pr * 2][1] = r1;
                bfr[pr * 2 + 1][0] = r2; bfr[pr * 2 + 1][1] = r3;
            }
#pragma unroll
            for (int im = 0; im < 4; im++)
#pragma unroll
                for (int jn = 0; jn < 8; jn++)
                    MMA16816(acc[im][jn], afr[im], bfr[jn]);
        }
    }

    // ---------------- fused epilogue ----------------
    const int base0 = nbase + wn * 64;
    const int hA = base0 / 96;
    float ps[4][2][2];
    float pd[4][2][2];
#pragma unroll
    for (int a = 0; a < 4; a++)
#pragma unroll
        for (int b = 0; b < 2; b++)
#pragma unroll
            for (int c = 0; c < 2; c++) { ps[a][b][c] = 0.f; pd[a][b][c] = 0.f; }

#pragma unroll
    for (int jn = 0; jn < 8; jn++) {
        int col = base0 + jn * 8 + (lane & 3) * 2;
        int slot = (col / 96) - hA;
        float as0 = __ldg(attS + col), as1 = __ldg(attS + col + 1);
        float ad0 = __ldg(attD + col), ad1 = __ldg(attD + col + 1);
#pragma unroll
        for (int im = 0; im < 4; im++) {
            int r0 = mbase + wm * 64 + im * 16 + (lane >> 2);
            if (r0 < NN)
                *(float2*)&d_g[(size_t)r0 * HIDD + col] =
                    make_float2(acc[im][jn][0], acc[im][jn][1]);
            if (r0 + 8 < NN)
                *(float2*)&d_g[(size_t)(r0 + 8) * HIDD + col] =
                    make_float2(acc[im][jn][2], acc[im][jn][3]);
            ps[im][0][slot] += acc[im][jn][0] * as0 + acc[im][jn][1] * as1;
            pd[im][0][slot] += acc[im][jn][0] * ad0 + acc[im][jn][1] * ad1;
            ps[im][1][slot] += acc[im][jn][2] * as0 + acc[im][jn][3] * as1;
            pd[im][1][slot] += acc[im][jn][2] * ad0 + acc[im][jn][3] * ad1;
        }
    }
#pragma unroll
    for (int im = 0; im < 4; im++)
#pragma unroll
        for (int rh = 0; rh < 2; rh++)
#pragma unroll
            for (int sl = 0; sl < 2; sl++) {
                float vs = ps[im][rh][sl], vd = pd[im][rh][sl];
                vs += __shfl_xor_sync(0xffffffffu, vs, 1);
                vs += __shfl_xor_sync(0xffffffffu, vs, 2);
                vd += __shfl_xor_sync(0xffffffffu, vd, 1);
                vd += __shfl_xor_sync(0xffffffffu, vd, 2);
                if ((lane & 3) == 0) {
                    int row = mbase + wm * 64 + im * 16 + (lane >> 2) + rh * 8;
                    int h = hA + sl;
                    if (row < NN && h < NH) {
                        atomicAdd(&asb[row * 8 + h], vs);
                        atomicAdd(&adb[row * 8 + h], vd);
                    }
                }
            }
}

// =====================================================================
// Attention: degree-sorted nodes (LPT), per-warp softmax + pair-balanced
// channel-split gather. block = 256 = 8 nodes via d_perm.
// =====================================================================
__global__ __launch_bounds__(256) void k_attn(
    const float* __restrict__ cas, const float* __restrict__ cad,
    float* __restrict__ nas, float* __restrict__ nad,
    const float* __restrict__ bias, int write_h)
{
    __shared__ float ebuf[8][MAXD * 8];
    __shared__ float smx[8][8];
    __shared__ float sinv[8][8];
    __shared__ int   snode[8];

    const int warp = threadIdx.x >> 5, lane = threadIdx.x & 31;
    const int blkbase = blockIdx.x * 8;
    const int n = d_perm[blkbase + warp];
    if (lane == 0) snode[warp] = n;

    if (lane < 8) { nas[n * 8 + lane] = 0.f; nad[n * 8 + lane] = 0.f; }

    const int beg = d_rowptr[n], end = d_rowptr[n + 1];
    const int deg = end - beg;

    const float4* adp = (const float4*)(cad + n * 8);
    float4 ad0 = adp[0], ad1 = adp[1];
    float ad[8] = {ad0.x, ad0.y, ad0.z, ad0.w, ad1.x, ad1.y, ad1.z, ad1.w};

    float mx[8];
#pragma unroll
    for (int h = 0; h < 8; h++) mx[h] = -1e30f;
    if (deg <= MAXD) {
#pragma unroll
        for (int it = 0; it < 2; it++) {
            int le = it * 32 + lane;
            if (le < deg) {
                int s = d_csrsrc[beg + le];
                const float4* ap = (const float4*)(cas + s * 8);
                float4 a0 = ap[0], a1 = ap[1];
                float ev[8] = {a0.x, a0.y, a0.z, a0.w, a1.x, a1.y, a1.z, a1.w};
#pragma unroll
                for (int h = 0; h < 8; h++) {
                    float e = ev[h] + ad[h];
                    e = e > 0.f ? e : 0.2f * e;
                    ebuf[warp][le * 8 + h] = e;
                    mx[h] = fmaxf(mx[h], e);
                }
            }
        }
    } else {
        for (int i0 = beg + lane; i0 < end; i0 += 32) {
            int s = d_csrsrc[i0];
            const float4* ap = (const float4*)(cas + s * 8);
            float4 a0 = ap[0], a1 = ap[1];
            float ev[8] = {a0.x, a0.y, a0.z, a0.w, a1.x, a1.y, a1.z, a1.w};
#pragma unroll
            for (int h = 0; h < 8; h++) {
                float e = ev[h] + ad[h];
                e = e > 0.f ? e : 0.2f * e;
                mx[h] = fmaxf(mx[h], e);
            }
        }
    }
#pragma unroll
    for (int h = 0; h < 8; h++)
        for (int off = 16; off; off >>= 1)
            mx[h] = fmaxf(mx[h], __shfl_xor_sync(0xffffffffu, mx[h], off));
    __syncwarp();

    float sm[8];
#pragma unroll
    for (int h = 0; h < 8; h++) sm[h] = 0.f;
    if (deg <= MAXD) {
#pragma unroll
        for (int it = 0; it < 2; it++) {
            int le = it * 32 + lane;
            if (le < deg) {
#pragma unroll
                for (int h = 0; h < 8; h++) {
                    float p = __expf(ebuf[warp][le * 8 + h] - mx[h]);
                    ebuf[warp][le * 8 + h] = p;
                    sm[h] += p;
                }
            }
        }
    } else {
        for (int i0 = beg + lane; i0 < end; i0 += 32) {
            int s = d_csrsrc[i0];
            const float4* ap = (const float4*)(cas + s * 8);
            float4 a0 = ap[0], a1 = ap[1];
            float ev[8] = {a0.x, a0.y, a0.z, a0.w, a1.x, a1.y, a1.z, a1.w};
#pragma unroll
            for (int h = 0; h < 8; h++) {
                float e = ev[h] + ad[h];
                e = e > 0.f ? e : 0.2f * e;
                sm[h] += __expf(e - mx[h]);
            }
        }
    }
#pragma unroll
    for (int h = 0; h < 8; h++)
        for (int off = 16; off; off >>= 1)
            sm[h] += __shfl_xor_sync(0xffffffffu, sm[h], off);
    float inv[8];
#pragma unroll
    for (int h = 0; h < 8; h++) inv[h] = 1.f / (sm[h] + 1e-16f);
    if (lane < 8) { smx[warp][lane] = mx[lane]; sinv[warp][lane] = inv[lane]; }
    __syncwarp();

    if (deg <= MAXD) {
#pragma unroll
        for (int it = 0; it < 2; it++) {
            int le = it * 32 + lane;
            if (le < deg) {
#pragma unroll
                for (int h = 0; h < 8; h++)
                    ebuf[warp][le * 8 + h] *= inv[h];
            }
        }
    }
    __syncthreads();

    const int pw = warp & 1;
    const int q0 = warp & ~1;
    int slot_t[3], head_t[3], j4_t[3];
#pragma unroll
    for (int t = 0; t < 3; t++) {
        slot_t[t] = pw * 3 + t;
        j4_t[t] = lane + 32 * slot_t[t];
        head_t[t] = j4_t[t] / 24;
    }

#pragma unroll
    for (int qi = 0; qi < 2; qi++) {
        int q = q0 + qi;
        int nq = snode[q];
        int bq = d_rowptr[nq], eq = d_rowptr[nq + 1];
        int dq = eq - bq;

        float4 acc4[3];
#pragma unroll
        for (int t = 0; t < 3; t++) acc4[t] = make_float4(0.f, 0.f, 0.f, 0.f);

        if (dq <= MAXD) {
            int le = 0;
            for (; le + 4 <= dq; le += 4) {
                int s0 = d_csrsrc[bq + le];
                int s1 = d_csrsrc[bq + le + 1];
                int s2 = d_csrsrc[bq + le + 2];
                int s3 = d_csrsrc[bq + le + 3];
                const float4* g0 = (const float4*)(d_g + (size_t)s0 * HIDD);
                const float4* g1 = (const float4*)(d_g + (size_t)s1 * HIDD);
                const float4* g2 = (const float4*)(d_g + (size_t)s2 * HIDD);
                const float4* g3 = (const float4*)(d_g + (size_t)s3 * HIDD);
#pragma unroll
                for (int t = 0; t < 3; t++) {
                    int j4 = j4_t[t], hh = head_t[t];
                    float a0 = ebuf[q][le * 8 + hh];
                    float a1 = ebuf[q][(le + 1) * 8 + hh];
                    float a2 = ebuf[q][(le + 2) * 8 + hh];
                    float a3 = ebuf[q][(le + 3) * 8 + hh];
                    float4 v0 = g0[j4], v1 = g1[j4], v2 = g2[j4], v3 = g3[j4];
                    acc4[t].x += a0 * v0.x + a1 * v1.x + a2 * v2.x + a3 * v3.x;
                    acc4[t].y += a0 * v0.y + a1 * v1.y + a2 * v2.y + a3 * v3.y;
                    acc4[t].z += a0 * v0.z + a1 * v1.z + a2 * v2.z + a3 * v3.z;
                    acc4[t].w += a0 * v0.w + a1 * v1.w + a2 * v2.w + a3 * v3.w;
                }
            }
            for (; le < dq; le++) {
                int s0 = d_csrsrc[bq + le];
                const float4* g0 = (const float4*)(d_g + (size_t)s0 * HIDD);
#pragma unroll
                for (int t = 0; t < 3; t++) {
                    float a0 = ebuf[q][le * 8 + head_t[t]];
                    float4 v0 = g0[j4_t[t]];
                    acc4[t].x += a0 * v0.x;
                    acc4[t].y += a0 * v0.y;
                    acc4[t].z += a0 * v0.z;
                    acc4[t].w += a0 * v0.w;
                }
            }
        } else {
            float adq[3], mxq[3], invq[3];
#pragma unroll
            for (int t = 0; t < 3; t++) {
                adq[t] = __ldg(cad + nq * 8 + head_t[t]);
                mxq[t] = smx[q][head_t[t]];
                invq[t] = sinv[q][head_t[t]];
            }
            for (int le = 0; le < dq; le++) {
                int s0 = d_csrsrc[bq + le];
                const float4* g0 = (const float4*)(d_g + (size_t)s0 * HIDD);
#pragma unroll
                for (int t = 0; t < 3; t++) {
                    float e = __ldg(cas + s0 * 8 + head_t[t]) + adq[t];
                    e = e > 0.f ? e : 0.2f * e;
                    float a0 = __expf(e - mxq[t]) * invq[t];
                    float4 v0 = g0[j4_t[t]];
                    acc4[t].x += a0 * v0.x;
                    acc4[t].y += a0 * v0.y;
                    acc4[t].z += a0 * v0.z;
                    acc4[t].w += a0 * v0.w;
                }
            }
        }

#pragma unroll
        for (int t = 0; t < 3; t++) {
            int j = 4 * j4_t[t];
            float4 b4 = *(const float4*)(bias + j);
            float4 v = acc4[t];
            v.x = fmaxf(v.x + b4.x, 0.f);
            v.y = fmaxf(v.y + b4.y, 0.f);
            v.z = fmaxf(v.z + b4.z, 0.f);
            v.w = fmaxf(v.w + b4.w, 0.f);
            if (write_h) *(float4*)&d_h[(size_t)nq * HIDD + j] = v;
            write_split4(nq, j, v);
        }
    }
}

// ---------------- pooling / fc ----------------
__global__ void k_pool() {
    int b = blockIdx.x;
    int j = blockIdx.y * 256 + threadIdx.x;
    int beg = d_gstart[b], end = d_gstart[b + 1];
    float s = 0.f;
    for (int n = beg; n < end; n++) s += d_h[(size_t)n * HIDD + j];
    float cnt = (float)(end - beg);
    d_pool[b * HIDD + j] = s / fmaxf(cnt, 1.0f);
}

__global__ void k_fc(const float* __restrict__ W, const float* __restrict__ b,
                     float* __restrict__ out) {
    int id = blockIdx.x * 256 + threadIdx.x;
    if (id >= NGB * EMB) return;
    int bb = id / EMB, k = id % EMB;
    float s = b[k];
    for (int j = 0; j < HIDD; j++) s += d_pool[bb * HIDD + j] * W[j * EMB + k];
    out[id] = s;
}

// ---------------- host launch ----------------
extern "C" void kernel_launch(void* const* d_in, const int* in_sizes, int n_in,
                              void* d_out, int out_size) {
    const float* x     = (const float*)d_in[0];
    const int*   ei    = (const int*)d_in[1];
    const int*   batch = (const int*)d_in[2];
    const float* projW = (const float*)d_in[3];
    const float* projb = (const float*)d_in[4];
    const float* convW = (const float*)d_in[5];
    const float* attS  = (const float*)d_in[6];
    const float* attD  = (const float*)d_in[7];
    const float* convb = (const float*)d_in[8];
    const float* fcW   = (const float*)d_in[9];
    const float* fcb   = (const float*)d_in[10];
    float* out = (float*)d_out;

    static bool attr_set = false;
    if (!attr_set) {
        cudaFuncSetAttribute(k_gemm_hmma, cudaFuncAttributeMaxDynamicSharedMemorySize, SMEM_GEMM);
        attr_set = true;
    }

    void* pW = nullptr;
    cudaGetSymbolAddress(&pW, d_WcatT);
    const __nv_bfloat16* Wcat = (const __nv_bfloat16*)pW;
    void *pa0, *pd0, *pa1, *pd1;
    cudaGetSymbolAddress(&pa0, d_as0);
    cudaGetSymbolAddress(&pd0, d_ad0);
    cudaGetSymbolAddress(&pa1, d_as1);
    cudaGetSymbolAddress(&pd1, d_ad1);
    float* asb[2] = {(float*)pa0, (float*)pa1};
    float* adb[2] = {(float*)pd0, (float*)pd1};

    k_zero_deg<<<(NN + 255) / 256, 256>>>();
    k_hist<<<(EA + 255) / 256, 256>>>(ei);
    k_scan<<<1, 1024>>>();
    k_scatter<<<(EA + 255) / 256, 256>>>(ei);
    k_dhist<<<(NN + 255) / 256, 256>>>();
    k_dscan<<<1, NB>>>();
    k_dscatter<<<(NN + 255) / 256, 256>>>();
    k_gstart<<<(NN + 255) / 256, 256>>>(batch);
    k_proj<<<(NN * HIDD + 255) / 256, 256>>>(x, projW, projb);
    k_split_w<<<(NL * HIDD * HIDD + 255) / 256, 256>>>(convW);
    k_zero_asd0<<<(NN * NH + 255) / 256, 256>>>();

    for (int l = 0; l < NL; l++) {
        int cur = l & 1, nxt = cur ^ 1;
        dim3 gg(HIDD / 128, (NN + 127) / 128);   // 6 x 157 = 942 CTAs
        k_gemm_hmma<<<gg, 128, SMEM_GEMM>>>(Wcat + (size_t)l * HIDD * KCAT,
                                            attS + l * HIDD, attD + l * HIDD,
                                            asb[cur], adb[cur]);
        k_attn<<<NN / 8, 256>>>(asb[cur], adb[cur], asb[nxt], adb[nxt],
                                convb + l * HIDD, (l == NL - 1) ? 1 : 0);
    }

    dim3 gp(NGB, 3);
    k_pool<<<gp, 256>>>();
    k_fc<<<(NGB * EMB + 255) / 256, 256>>>(fcW, fcb, out);
}